// round 4
// baseline (speedup 1.0000x reference)
#include <cuda_runtime.h>
#include <math.h>

// Problem constants
#define BSZ   32
#define TLEN  1024
#define DIN   768
#define HD    768
#define G3    2304          // 3*HD
#define FCN   512
#define NOUTC 39

typedef unsigned long long ull;

// ---------------------------------------------------------------------------
// Scratch (device globals; no allocation allowed)
// ---------------------------------------------------------------------------
__device__ float g_xproj[(size_t)BSZ * TLEN * G3];   // input projections [B,T,3H]
__device__ float g_hall [(size_t)BSZ * TLEN * HD];   // GRU outputs [B,T,H]
__device__ float g_fc   [(size_t)BSZ * TLEN * FCN];  // fc output

// Grid-barrier flags: monotonic, never reset -> all equal at launch boundaries,
// deterministic across graph replays.
__device__ unsigned g_flags[96];

// ---------------------------------------------------------------------------
// Packed fp32x2 FMA helpers
// ---------------------------------------------------------------------------
__device__ __forceinline__ void fma2(ull& d, ull a, ull b) {
    asm("fma.rn.f32x2 %0, %1, %2, %0;" : "+l"(d) : "l"(a), "l"(b));
}
__device__ __forceinline__ ull pack2(float lo, float hi) {
    ull d;
    asm("mov.b64 %0, {%1, %2};" : "=l"(d) : "f"(lo), "f"(hi));
    return d;
}
__device__ __forceinline__ float2 unpack2(ull v) {
    float2 r;
    asm("mov.b64 {%0, %1}, %2;" : "=f"(r.x), "=f"(r.y) : "l"(v));
    return r;
}

// cp.async 16B, L2-only (.cg) — bypasses L1 so cross-block h hand-off is safe.
__device__ __forceinline__ void cp16(void* smem_dst, const void* gsrc) {
    unsigned s = (unsigned)__cvta_generic_to_shared(smem_dst);
    asm volatile("cp.async.cg.shared.global [%0], [%1], 16;" :: "r"(s), "l"(gsrc));
}
__device__ __forceinline__ void cp_commit() {
    asm volatile("cp.async.commit_group;");
}
template <int N>
__device__ __forceinline__ void cp_wait() {
    asm volatile("cp.async.wait_group %0;" :: "n"(N));
}

// ---------------------------------------------------------------------------
// Generic fp32 GEMM: C[M,N] = act(A[M,K] @ W[N,K]^T + bias[N])   (unchanged)
// ---------------------------------------------------------------------------
template <int ACT>
__global__ __launch_bounds__(256) void gemm_bias_act(
    const float* __restrict__ A,
    const float* __restrict__ W,
    const float* __restrict__ bias,
    float* __restrict__ C,
    int M, int N, int K)
{
    __shared__ float As[8][128];
    __shared__ float Bs[8][128];

    const int tid  = threadIdx.x;
    const int m0   = blockIdx.y * 128;
    const int n0   = blockIdx.x * 128;

    const int lrow = tid >> 1;
    const int lk4  = (tid & 1) * 4;

    const int tx = tid & 15;
    const int ty = tid >> 4;

    ull acc2[8][4];
#pragma unroll
    for (int i = 0; i < 8; i++)
#pragma unroll
        for (int j = 0; j < 4; j++) acc2[i][j] = 0ull;

    const float* Arow = A + (size_t)(m0 + lrow) * K + lk4;
    const float* Wrow = W + (size_t)(n0 + lrow) * K + lk4;
    const bool   wok  = (n0 + lrow) < N;

    for (int k0 = 0; k0 < K; k0 += 8) {
        float4 av = *(const float4*)(Arow + k0);
        float4 wv = make_float4(0.f, 0.f, 0.f, 0.f);
        if (wok) wv = *(const float4*)(Wrow + k0);

        __syncthreads();
        As[lk4 + 0][lrow] = av.x; As[lk4 + 1][lrow] = av.y;
        As[lk4 + 2][lrow] = av.z; As[lk4 + 3][lrow] = av.w;
        Bs[lk4 + 0][lrow] = wv.x; Bs[lk4 + 1][lrow] = wv.y;
        Bs[lk4 + 2][lrow] = wv.z; Bs[lk4 + 3][lrow] = wv.w;
        __syncthreads();

#pragma unroll
        for (int kk = 0; kk < 8; kk++) {
            float a[8];
            *(float4*)(a)     = *(const float4*)&As[kk][ty * 4];
            *(float4*)(a + 4) = *(const float4*)&As[kk][64 + ty * 4];
            ulonglong2 b01 = *(const ulonglong2*)&Bs[kk][tx * 4];
            ulonglong2 b23 = *(const ulonglong2*)&Bs[kk][64 + tx * 4];
            ull bb[4] = { b01.x, b01.y, b23.x, b23.y };
            ull aa[8];
#pragma unroll
            for (int i = 0; i < 8; i++) aa[i] = pack2(a[i], a[i]);
#pragma unroll
            for (int i = 0; i < 8; i++)
#pragma unroll
                for (int j = 0; j < 4; j++)
                    fma2(acc2[i][j], aa[i], bb[j]);
        }
    }

    const float selu_scale = 1.0507009873554804934193349852946f;
    const float selu_alpha = 1.6732632423543772848170429916717f;

#pragma unroll
    for (int i = 0; i < 8; i++) {
        const int m = m0 + ((i < 4) ? (ty * 4 + i) : (64 + ty * 4 + i - 4));
        float* crow = C + (size_t)m * N;
#pragma unroll
        for (int j = 0; j < 4; j++) {
            const int nf = n0 + ((j < 2) ? (tx * 4 + j * 2)
                                         : (64 + tx * 4 + (j - 2) * 2));
            float2 v = unpack2(acc2[i][j]);
            float vals[2] = { v.x, v.y };
#pragma unroll
            for (int s = 0; s < 2; s++) {
                const int n = nf + s;
                if (n < N) {
                    float val = vals[s] + bias[n];
                    if (ACT == 1) {
                        val = selu_scale * (val > 0.f ? val
                                                      : selu_alpha * (expf(val) - 1.f));
                    } else if (ACT == 2) {
                        val = tanhf(val);
                    }
                    crow[n] = val;
                }
            }
        }
    }
}

// ---------------------------------------------------------------------------
// Persistent GRU layer kernel.
// 96 blocks x 256 threads; block owns NU=8 hidden units (24 gh rows).
// Per step:
//   cp.async stage h_{t-1} in 2 k-halves (overlapped with GEMM of half 0),
//   GEMM micro-tile 8 batches x 12 rows over 24-k interleaved slices (nks=32),
//   rotated-layout smem reduction (aliases sh_h), gates, flag barrier.
// ---------------------------------------------------------------------------
#define NBLK      96
#define NU        8
#define NROWS     24
#define HPITCH    772                        // floats; 772*4 % 16 == 0
#define SH_H_FL   (32 * HPITCH)              // 24704 floats (98816 B)
#define SH_W_FL   (NROWS * HPITCH)           // 18528 floats (74112 B)
#define STEP_SMEM ((SH_H_FL + SH_W_FL) * sizeof(float))   // 172928 B

__global__ __launch_bounds__(256) void gru_layer_persistent(
    const float* __restrict__ xproj,   // [B,T,3H] (gi, b_ih folded in)
    const float* __restrict__ w_hh,    // [3H, H]
    const float* __restrict__ b_hh,    // [3H]
    float* __restrict__ h_all)         // [B,T,H]
{
    extern __shared__ float sm[];
    float* sh_h = sm;                       // [32][HPITCH]
    float* sh_w = sm + SH_H_FL;             // [24][HPITCH]
    float* sh_r = sm;                       // reduction buffer ALIASES sh_h

    const int tid = threadIdx.x;
    const int u0  = blockIdx.x * NU;

    const unsigned flag_base = g_flags[blockIdx.x];   // own flag: no race

    // --- one-time: load w_hh slice (row lr -> gate = lr>>3, unit = lr&7) ---
    for (int i = tid; i < NROWS * 192; i += 256) {
        const int lr = i / 192;
        const int k4 = (i % 192) * 4;
        const int gate = lr >> 3;
        const int u    = lr & 7;
        const float4 v = *(const float4*)(w_hh + (size_t)(gate * HD + u0 + u) * HD + k4);
        float* dst = sh_w + lr * HPITCH + k4;
        dst[0] = v.x; dst[1] = v.y; dst[2] = v.z; dst[3] = v.w;
    }

    // GEMM decode: ks (k-slice 0..31), bq (batch group 0..3), rq (row group 0..1)
    const int ks = tid & 31;
    const int bq = (tid >> 5) & 3;
    const int rq = tid >> 7;
    const float* hp = sh_h + (bq * 8) * HPITCH + ks * 4;
    const float* wp = sh_w + (rq * 12) * HPITCH + ks * 4;

    // Gate decode
    const int bg = tid >> 3;          // batch 0..31
    const int ug = tid & 7;           // unit 0..7
    const float bias_r = b_hh[u0 + ug];
    const float bias_z = b_hh[HD + u0 + ug];
    const float bias_n = b_hh[2 * HD + u0 + ug];
    const size_t hrow  = (size_t)bg * TLEN;

    // ---------------- t = 0: h_prev = 0 -> gh = bias only ----------------
    {
        const size_t xbase = (hrow + 0) * G3 + (u0 + ug);
        const float gi_r = xproj[xbase];
        const float gi_z = xproj[xbase + HD];
        const float gi_n = xproj[xbase + 2 * HD];
        const float r = 1.f / (1.f + expf(-(gi_r + bias_r)));
        const float z = 1.f / (1.f + expf(-(gi_z + bias_z)));
        const float n = tanhf(gi_n + r * bias_n);
        h_all[(hrow + 0) * HD + (u0 + ug)] = (1.f - z) * n;   // z*0 = 0
        __syncthreads();
        const unsigned target = flag_base + 1u;
        if (tid == 0)
            asm volatile("st.release.gpu.global.u32 [%0], %1;"
                         :: "l"(&g_flags[blockIdx.x]), "r"(target) : "memory");
        if (tid < NBLK) {
            unsigned v;
            do {
                asm volatile("ld.acquire.gpu.global.u32 %0, [%1];"
                             : "=r"(v) : "l"(&g_flags[tid]) : "memory");
            } while ((int)(v - target) < 0);
        }
        __syncthreads();
    }

    // ---------------- t = 1 .. TLEN-1 ----------------
    for (int t = 1; t < TLEN; t++) {
        // --- stage h_{t-1}: 2 halves of 3072 float4 via cp.async ---
        const float* hsrc = h_all + (size_t)(t - 1) * HD;   // + b*TLEN*HD per row
#pragma unroll
        for (int n = 0; n < 12; n++) {
            const int i   = tid + n * 256;      // 0..3071
            const int row = i / 96;
            const int c4  = (i % 96) * 4;       // k offset (half 0)
            cp16(sh_h + row * HPITCH + c4,
                 hsrc + (size_t)row * TLEN * HD + c4);
        }
        cp_commit();
#pragma unroll
        for (int n = 0; n < 12; n++) {
            const int i   = tid + n * 256;
            const int row = i / 96;
            const int c4  = (i % 96) * 4 + 384;  // half 1
            cp16(sh_h + row * HPITCH + c4,
                 hsrc + (size_t)row * TLEN * HD + c4);
        }
        cp_commit();

        // gate-input prefetch (global, independent; overlaps everything)
        const size_t xbase = (hrow + t) * G3 + (u0 + ug);
        const float gi_r = xproj[xbase];
        const float gi_z = xproj[xbase + HD];
        const float gi_n = xproj[xbase + 2 * HD];

        ull acc2[8][12];
#pragma unroll
        for (int i = 0; i < 8; i++)
#pragma unroll
            for (int j = 0; j < 12; j++) acc2[i][j] = 0ull;

        // half 0 ready
        cp_wait<1>();
        __syncthreads();

#pragma unroll
        for (int j = 0; j < 3; j++) {
            const int kb = j * 128;
            ulonglong2 h2[8];
#pragma unroll
            for (int i = 0; i < 8; i++)
                h2[i] = *(const ulonglong2*)(hp + i * HPITCH + kb);
#pragma unroll
            for (int jj = 0; jj < 12; jj++) {
                const ulonglong2 w2 = *(const ulonglong2*)(wp + jj * HPITCH + kb);
#pragma unroll
                for (int i = 0; i < 8; i++) {
                    fma2(acc2[i][jj], h2[i].x, w2.x);
                    fma2(acc2[i][jj], h2[i].y, w2.y);
                }
            }
        }

        // half 1 ready
        cp_wait<0>();
        __syncthreads();

#pragma unroll
        for (int j = 3; j < 6; j++) {
            const int kb = j * 128;
            ulonglong2 h2[8];
#pragma unroll
            for (int i = 0; i < 8; i++)
                h2[i] = *(const ulonglong2*)(hp + i * HPITCH + kb);
#pragma unroll
            for (int jj = 0; jj < 12; jj++) {
                const ulonglong2 w2 = *(const ulonglong2*)(wp + jj * HPITCH + kb);
#pragma unroll
                for (int i = 0; i < 8; i++) {
                    fma2(acc2[i][jj], h2[i].x, w2.x);
                    fma2(acc2[i][jj], h2[i].y, w2.y);
                }
            }
        }

        // read hprev before sh_h is overwritten by the reduction dump
        const float hprev = sh_h[bg * HPITCH + u0 + ug];
        __syncthreads();

        // --- dump partials into rotated layout (conflict-free both ways) ---
#pragma unroll
        for (int i = 0; i < 8; i++) {
            const int b = bq * 8 + i;
#pragma unroll
            for (int jj = 0; jj < 12; jj++) {
                const int out = b * NROWS + rq * 12 + jj;
                const float2 p = unpack2(acc2[i][jj]);
                sh_r[out * 32 + ((ks + 4 * out) & 31)] = p.x + p.y;
            }
        }
        __syncthreads();

        // --- gates ---
        {
            float gh[3];
#pragma unroll
            for (int g = 0; g < 3; g++) {
                const int out = bg * NROWS + g * 8 + ug;
                const float* rp = sh_r + out * 32;
                float s = 0.f;
#pragma unroll
                for (int p = 0; p < 8; p++) {
                    const int off = (4 * p + 4 * out) & 31;
                    const float4 v = *(const float4*)(rp + off);
                    s += (v.x + v.y) + (v.z + v.w);
                }
                gh[g] = s;
            }
            const float r = 1.f / (1.f + expf(-(gi_r + gh[0] + bias_r)));
            const float z = 1.f / (1.f + expf(-(gi_z + gh[1] + bias_z)));
            const float n = tanhf(gi_n + r * (gh[2] + bias_n));
            const float hnew = (1.f - z) * n + z * hprev;
            h_all[(hrow + t) * HD + (u0 + ug)] = hnew;
        }
        __syncthreads();   // all h_t stores before release; sh_r reads done

        // --- grid barrier ---
        const unsigned target = flag_base + (unsigned)(t + 1);
        if (tid == 0)
            asm volatile("st.release.gpu.global.u32 [%0], %1;"
                         :: "l"(&g_flags[blockIdx.x]), "r"(target) : "memory");
        if (tid < NBLK) {
            unsigned v;
            do {
                asm volatile("ld.acquire.gpu.global.u32 %0, [%1];"
                             : "=r"(v) : "l"(&g_flags[tid]) : "memory");
            } while ((int)(v - target) < 0);
        }
        __syncthreads();
    }
}

// ---------------------------------------------------------------------------
// Launch: 6 graph nodes.
// ---------------------------------------------------------------------------
extern "C" void kernel_launch(void* const* d_in, const int* in_sizes, int n_in,
                              void* d_out, int out_size)
{
    const float* features = (const float*)d_in[0];
    const float* w_ih0 = (const float*)d_in[2];
    const float* w_hh0 = (const float*)d_in[3];
    const float* b_ih0 = (const float*)d_in[4];
    const float* b_hh0 = (const float*)d_in[5];
    const float* w_ih1 = (const float*)d_in[6];
    const float* w_hh1 = (const float*)d_in[7];
    const float* b_ih1 = (const float*)d_in[8];
    const float* b_hh1 = (const float*)d_in[9];
    const float* fc_w  = (const float*)d_in[10];
    const float* fc_b  = (const float*)d_in[11];
    const float* out_w = (const float*)d_in[12];
    const float* out_b = (const float*)d_in[13];

    float *xproj, *hall, *fcb;
    cudaGetSymbolAddress((void**)&xproj, g_xproj);
    cudaGetSymbolAddress((void**)&hall,  g_hall);
    cudaGetSymbolAddress((void**)&fcb,   g_fc);

    static bool attr_set = false;
    if (!attr_set) {
        cudaFuncSetAttribute(gru_layer_persistent,
                             cudaFuncAttributeMaxDynamicSharedMemorySize,
                             (int)STEP_SMEM);
        attr_set = true;
    }

    const int M = BSZ * TLEN;                 // 32768

    // Layer 0: input projection (b_ih folded in)
    {
        dim3 grid(G3 / 128, M / 128);
        gemm_bias_act<0><<<grid, 256>>>(features, w_ih0, b_ih0, xproj, M, G3, DIN);
    }
    gru_layer_persistent<<<NBLK, 256, STEP_SMEM>>>(xproj, w_hh0, b_hh0, hall);

    // Layer 1
    {
        dim3 grid(G3 / 128, M / 128);
        gemm_bias_act<0><<<grid, 256>>>(hall, w_ih1, b_ih1, xproj, M, G3, HD);
    }
    gru_layer_persistent<<<NBLK, 256, STEP_SMEM>>>(xproj, w_hh1, b_hh1, hall);

    // fc + SELU
    {
        dim3 grid(FCN / 128, M / 128);
        gemm_bias_act<1><<<grid, 256>>>(hall, fc_w, fc_b, fcb, M, FCN, HD);
    }
    // out_proj + tanh
    {
        dim3 grid((NOUTC + 127) / 128, M / 128);
        gemm_bias_act<2><<<grid, 256>>>(fcb, out_w, out_b, (float*)d_out, M, NOUTC, FCN);
    }
}

// round 5
// speedup vs baseline: 1.2392x; 1.2392x over previous
#include <cuda_runtime.h>
#include <math.h>

// Problem constants
#define BSZ   32
#define TLEN  1024
#define DIN   768
#define HD    768
#define G3    2304          // 3*HD
#define FCN   512
#define NOUTC 39

typedef unsigned long long ull;

// ---------------------------------------------------------------------------
// Scratch (device globals; no allocation allowed)
// ---------------------------------------------------------------------------
__device__ float g_xproj[(size_t)BSZ * TLEN * G3];   // input projections [B,T,3H]
__device__ float g_hall [(size_t)BSZ * TLEN * HD];   // GRU outputs [B,T,H]
__device__ float g_fc   [(size_t)BSZ * TLEN * FCN];  // fc output

// Grid-barrier flags: monotonic, never reset -> equal at launch boundaries,
// deterministic across graph replays.
__device__ unsigned g_flags[96];

// ---------------------------------------------------------------------------
// Packed fp32x2 FMA helpers
// ---------------------------------------------------------------------------
__device__ __forceinline__ void fma2(ull& d, ull a, ull b) {
    asm("fma.rn.f32x2 %0, %1, %2, %0;" : "+l"(d) : "l"(a), "l"(b));
}
__device__ __forceinline__ ull pack2(float lo, float hi) {
    ull d;
    asm("mov.b64 %0, {%1, %2};" : "=l"(d) : "f"(lo), "f"(hi));
    return d;
}
__device__ __forceinline__ float2 unpack2(ull v) {
    float2 r;
    asm("mov.b64 {%0, %1}, %2;" : "=f"(r.x), "=f"(r.y) : "l"(v));
    return r;
}

// cp.async 16B, L2-only (.cg): bypasses L1 so cross-SM h hand-off is safe.
__device__ __forceinline__ void cp16(void* smem_dst, const void* gsrc) {
    unsigned s = (unsigned)__cvta_generic_to_shared(smem_dst);
    asm volatile("cp.async.cg.shared.global [%0], [%1], 16;" :: "r"(s), "l"(gsrc));
}
__device__ __forceinline__ void cp_commit() {
    asm volatile("cp.async.commit_group;");
}
template <int N>
__device__ __forceinline__ void cp_wait() {
    asm volatile("cp.async.wait_group %0;" :: "n"(N));
}

// ---------------------------------------------------------------------------
// Generic fp32 GEMM: C[M,N] = act(A[M,K] @ W[N,K]^T + bias[N])   (unchanged)
// ---------------------------------------------------------------------------
template <int ACT>
__global__ __launch_bounds__(256) void gemm_bias_act(
    const float* __restrict__ A,
    const float* __restrict__ W,
    const float* __restrict__ bias,
    float* __restrict__ C,
    int M, int N, int K)
{
    __shared__ float As[8][128];
    __shared__ float Bs[8][128];

    const int tid  = threadIdx.x;
    const int m0   = blockIdx.y * 128;
    const int n0   = blockIdx.x * 128;

    const int lrow = tid >> 1;
    const int lk4  = (tid & 1) * 4;

    const int tx = tid & 15;
    const int ty = tid >> 4;

    ull acc2[8][4];
#pragma unroll
    for (int i = 0; i < 8; i++)
#pragma unroll
        for (int j = 0; j < 4; j++) acc2[i][j] = 0ull;

    const float* Arow = A + (size_t)(m0 + lrow) * K + lk4;
    const float* Wrow = W + (size_t)(n0 + lrow) * K + lk4;
    const bool   wok  = (n0 + lrow) < N;

    for (int k0 = 0; k0 < K; k0 += 8) {
        float4 av = *(const float4*)(Arow + k0);
        float4 wv = make_float4(0.f, 0.f, 0.f, 0.f);
        if (wok) wv = *(const float4*)(Wrow + k0);

        __syncthreads();
        As[lk4 + 0][lrow] = av.x; As[lk4 + 1][lrow] = av.y;
        As[lk4 + 2][lrow] = av.z; As[lk4 + 3][lrow] = av.w;
        Bs[lk4 + 0][lrow] = wv.x; Bs[lk4 + 1][lrow] = wv.y;
        Bs[lk4 + 2][lrow] = wv.z; Bs[lk4 + 3][lrow] = wv.w;
        __syncthreads();

#pragma unroll
        for (int kk = 0; kk < 8; kk++) {
            float a[8];
            *(float4*)(a)     = *(const float4*)&As[kk][ty * 4];
            *(float4*)(a + 4) = *(const float4*)&As[kk][64 + ty * 4];
            ulonglong2 b01 = *(const ulonglong2*)&Bs[kk][tx * 4];
            ulonglong2 b23 = *(const ulonglong2*)&Bs[kk][64 + tx * 4];
            ull bb[4] = { b01.x, b01.y, b23.x, b23.y };
            ull aa[8];
#pragma unroll
            for (int i = 0; i < 8; i++) aa[i] = pack2(a[i], a[i]);
#pragma unroll
            for (int i = 0; i < 8; i++)
#pragma unroll
                for (int j = 0; j < 4; j++)
                    fma2(acc2[i][j], aa[i], bb[j]);
        }
    }

    const float selu_scale = 1.0507009873554804934193349852946f;
    const float selu_alpha = 1.6732632423543772848170429916717f;

#pragma unroll
    for (int i = 0; i < 8; i++) {
        const int m = m0 + ((i < 4) ? (ty * 4 + i) : (64 + ty * 4 + i - 4));
        float* crow = C + (size_t)m * N;
#pragma unroll
        for (int j = 0; j < 4; j++) {
            const int nf = n0 + ((j < 2) ? (tx * 4 + j * 2)
                                         : (64 + tx * 4 + (j - 2) * 2));
            float2 v = unpack2(acc2[i][j]);
            float vals[2] = { v.x, v.y };
#pragma unroll
            for (int s = 0; s < 2; s++) {
                const int n = nf + s;
                if (n < N) {
                    float val = vals[s] + bias[n];
                    if (ACT == 1) {
                        val = selu_scale * (val > 0.f ? val
                                                      : selu_alpha * (expf(val) - 1.f));
                    } else if (ACT == 2) {
                        val = tanhf(val);
                    }
                    crow[n] = val;
                }
            }
        }
    }
}

// ---------------------------------------------------------------------------
// Persistent GRU layer kernel.
// 96 blocks x 256 threads; block owns NU=8 hidden units (24 gh rows).
// Per step: parallel flag poll (tid<96, one flag each), cp.async.cg staging of
// h_{t-1} in 2 k-halves overlapped with the 2 GEMM halves, micro-tile
// 8 batches x 6 rows over 16 interleaved k-slices (96 acc regs, no spills),
// smem K-reduction (RPITCH=17), gates, release own flag.
// ---------------------------------------------------------------------------
#define NBLK      96
#define NU        8
#define NROWS     24
#define HPITCH    772                        // floats; 772*4 % 16 == 0
#define RPITCH    17
#define SH_H_FL   (32 * HPITCH)              // 24704 floats (98816 B)
#define SH_W_FL   (NROWS * HPITCH)           // 18528 floats (74112 B)
#define STEP_SMEM ((SH_H_FL + SH_W_FL) * sizeof(float))   // 172928 B

__global__ __launch_bounds__(256) void gru_layer_persistent(
    const float* __restrict__ xproj,   // [B,T,3H] (gi, b_ih folded in)
    const float* __restrict__ w_hh,    // [3H, H]
    const float* __restrict__ b_hh,    // [3H]
    float* __restrict__ h_all)         // [B,T,H]
{
    extern __shared__ float sm[];
    float* sh_h = sm;                       // [32][HPITCH]
    float* sh_w = sm + SH_H_FL;             // [24][HPITCH]
    float* sh_r = sm;                       // reduction buffer ALIASES sh_h

    const int tid = threadIdx.x;
    const int u0  = blockIdx.x * NU;

    const unsigned flag_base = g_flags[blockIdx.x];   // own flag: no race

    // --- one-time: load w_hh slice (row lr -> gate = lr>>3, unit = lr&7) ---
    for (int i = tid; i < NROWS * 192; i += 256) {
        const int lr = i / 192;
        const int k4 = (i % 192) * 4;
        const int gate = lr >> 3;
        const int u    = lr & 7;
        const float4 v = *(const float4*)(w_hh + (size_t)(gate * HD + u0 + u) * HD + k4);
        float* dst = sh_w + lr * HPITCH + k4;
        dst[0] = v.x; dst[1] = v.y; dst[2] = v.z; dst[3] = v.w;
    }

    // GEMM decode (round-3 proven): ks 0..15, bq 0..3, rq 0..3
    const int ks = tid & 15;          // 16 interleaved k-slices (k = 4*ks + 64*j)
    const int bq = (tid >> 4) & 3;    // 4 groups of 8 batches
    const int rq = tid >> 6;          // 4 groups of 6 rows
    const float* hp = sh_h + (bq * 8) * HPITCH + ks * 4;
    const float* wp = sh_w + (rq * 6) * HPITCH + ks * 4;

    // Gate decode
    const int bg = tid >> 3;          // batch 0..31
    const int ug = tid & 7;           // unit 0..7
    const float bias_r = b_hh[u0 + ug];
    const float bias_z = b_hh[HD + u0 + ug];
    const float bias_n = b_hh[2 * HD + u0 + ug];
    const size_t hrow  = (size_t)bg * TLEN;

    // ---------------- t = 0: h_prev = 0 -> gh = bias only ----------------
    {
        const size_t xbase = (hrow + 0) * G3 + (u0 + ug);
        const float gi_r = xproj[xbase];
        const float gi_z = xproj[xbase + HD];
        const float gi_n = xproj[xbase + 2 * HD];
        const float r = 1.f / (1.f + expf(-(gi_r + bias_r)));
        const float z = 1.f / (1.f + expf(-(gi_z + bias_z)));
        const float n = tanhf(gi_n + r * bias_n);
        h_all[(hrow + 0) * HD + (u0 + ug)] = (1.f - z) * n;   // z*0 = 0
        __syncthreads();
        if (tid == 0)
            asm volatile("st.release.gpu.global.u32 [%0], %1;"
                         :: "l"(&g_flags[blockIdx.x]), "r"(flag_base + 1u) : "memory");
    }

    // ---------------- t = 1 .. TLEN-1 ----------------
    for (int t = 1; t < TLEN; t++) {
        // --- wait for all blocks' h_{t-1} (parallel: one flag per thread) ---
        const unsigned need = flag_base + (unsigned)t;
        if (tid < NBLK) {
            unsigned v;
            do {
                asm volatile("ld.acquire.gpu.global.u32 %0, [%1];"
                             : "=r"(v) : "l"(&g_flags[tid]) : "memory");
            } while ((int)(v - need) < 0);
        }
        __syncthreads();

        // --- stage h_{t-1}: 2 halves of 3072 float4 via cp.async.cg ---
        const float* hsrc = h_all + (size_t)(t - 1) * HD;   // + b*TLEN*HD per row
#pragma unroll
        for (int n = 0; n < 12; n++) {
            const int i   = tid + n * 256;      // 0..3071
            const int row = i / 96;
            const int c4  = (i % 96) * 4;       // k offset (half 0: k < 384)
            cp16(sh_h + row * HPITCH + c4,
                 hsrc + (size_t)row * TLEN * HD + c4);
        }
        cp_commit();
#pragma unroll
        for (int n = 0; n < 12; n++) {
            const int i   = tid + n * 256;
            const int row = i / 96;
            const int c4  = (i % 96) * 4 + 384;  // half 1: k >= 384
            cp16(sh_h + row * HPITCH + c4,
                 hsrc + (size_t)row * TLEN * HD + c4);
        }
        cp_commit();

        // gate-input prefetch (independent; overlaps staging + GEMM)
        const size_t xbase = (hrow + t) * G3 + (u0 + ug);
        const float gi_r = xproj[xbase];
        const float gi_z = xproj[xbase + HD];
        const float gi_n = xproj[xbase + 2 * HD];

        ull acc2[8][6];
#pragma unroll
        for (int i = 0; i < 8; i++)
#pragma unroll
            for (int j = 0; j < 6; j++) acc2[i][j] = 0ull;

        // half 0 ready
        cp_wait<1>();
        __syncthreads();

#pragma unroll
        for (int j = 0; j < 6; j++) {              // k = 4*ks + 64*j, k < 384
            const int kb = j * 64;
            ulonglong2 h2[8];
#pragma unroll
            for (int i = 0; i < 8; i++)
                h2[i] = *(const ulonglong2*)(hp + i * HPITCH + kb);
#pragma unroll
            for (int jj = 0; jj < 6; jj++) {
                const ulonglong2 w2 = *(const ulonglong2*)(wp + jj * HPITCH + kb);
#pragma unroll
                for (int i = 0; i < 8; i++) {
                    fma2(acc2[i][jj], h2[i].x, w2.x);
                    fma2(acc2[i][jj], h2[i].y, w2.y);
                }
            }
        }

        // half 1 ready
        cp_wait<0>();
        __syncthreads();

#pragma unroll
        for (int j = 6; j < 12; j++) {             // k >= 384
            const int kb = j * 64;
            ulonglong2 h2[8];
#pragma unroll
            for (int i = 0; i < 8; i++)
                h2[i] = *(const ulonglong2*)(hp + i * HPITCH + kb);
#pragma unroll
            for (int jj = 0; jj < 6; jj++) {
                const ulonglong2 w2 = *(const ulonglong2*)(wp + jj * HPITCH + kb);
#pragma unroll
                for (int i = 0; i < 8; i++) {
                    fma2(acc2[i][jj], h2[i].x, w2.x);
                    fma2(acc2[i][jj], h2[i].y, w2.y);
                }
            }
        }

        // read hprev before sh_h is overwritten by the reduction dump
        const float hprev = sh_h[bg * HPITCH + u0 + ug];
        __syncthreads();

        // --- dump partials: sh_r[(b*24 + lr)*17 + ks] (round-3 layout) ---
#pragma unroll
        for (int i = 0; i < 8; i++) {
            const int b = bq * 8 + i;
#pragma unroll
            for (int jj = 0; jj < 6; jj++) {
                const int lr = rq * 6 + jj;
                const float2 p = unpack2(acc2[i][jj]);
                sh_r[(b * NROWS + lr) * RPITCH + ks] = p.x + p.y;
            }
        }
        __syncthreads();

        // --- gates ---
        {
            float gh[3];
#pragma unroll
            for (int g = 0; g < 3; g++) {
                const int out = bg * NROWS + g * 8 + ug;
                float s = 0.f;
#pragma unroll
                for (int p = 0; p < 16; p++) s += sh_r[out * RPITCH + p];
                gh[g] = s;
            }
            const float r = 1.f / (1.f + expf(-(gi_r + gh[0] + bias_r)));
            const float z = 1.f / (1.f + expf(-(gi_z + gh[1] + bias_z)));
            const float n = tanhf(gi_n + r * (gh[2] + bias_n));
            const float hnew = (1.f - z) * n + z * hprev;
            h_all[(hrow + t) * HD + (u0 + ug)] = hnew;
        }
        __syncthreads();   // all h_t stores done before release

        if (tid == 0)
            asm volatile("st.release.gpu.global.u32 [%0], %1;"
                         :: "l"(&g_flags[blockIdx.x]),
                            "r"(flag_base + (unsigned)(t + 1)) : "memory");
    }
}

// ---------------------------------------------------------------------------
// Launch: 6 graph nodes.
// ---------------------------------------------------------------------------
extern "C" void kernel_launch(void* const* d_in, const int* in_sizes, int n_in,
                              void* d_out, int out_size)
{
    const float* features = (const float*)d_in[0];
    const float* w_ih0 = (const float*)d_in[2];
    const float* w_hh0 = (const float*)d_in[3];
    const float* b_ih0 = (const float*)d_in[4];
    const float* b_hh0 = (const float*)d_in[5];
    const float* w_ih1 = (const float*)d_in[6];
    const float* w_hh1 = (const float*)d_in[7];
    const float* b_ih1 = (const float*)d_in[8];
    const float* b_hh1 = (const float*)d_in[9];
    const float* fc_w  = (const float*)d_in[10];
    const float* fc_b  = (const float*)d_in[11];
    const float* out_w = (const float*)d_in[12];
    const float* out_b = (const float*)d_in[13];

    float *xproj, *hall, *fcb;
    cudaGetSymbolAddress((void**)&xproj, g_xproj);
    cudaGetSymbolAddress((void**)&hall,  g_hall);
    cudaGetSymbolAddress((void**)&fcb,   g_fc);

    static bool attr_set = false;
    if (!attr_set) {
        cudaFuncSetAttribute(gru_layer_persistent,
                             cudaFuncAttributeMaxDynamicSharedMemorySize,
                             (int)STEP_SMEM);
        attr_set = true;
    }

    const int M = BSZ * TLEN;                 // 32768

    // Layer 0: input projection (b_ih folded in)
    {
        dim3 grid(G3 / 128, M / 128);
        gemm_bias_act<0><<<grid, 256>>>(features, w_ih0, b_ih0, xproj, M, G3, DIN);
    }
    gru_layer_persistent<<<NBLK, 256, STEP_SMEM>>>(xproj, w_hh0, b_hh0, hall);

    // Layer 1
    {
        dim3 grid(G3 / 128, M / 128);
        gemm_bias_act<0><<<grid, 256>>>(hall, w_ih1, b_ih1, xproj, M, G3, HD);
    }
    gru_layer_persistent<<<NBLK, 256, STEP_SMEM>>>(xproj, w_hh1, b_hh1, hall);

    // fc + SELU
    {
        dim3 grid(FCN / 128, M / 128);
        gemm_bias_act<1><<<grid, 256>>>(hall, fc_w, fc_b, fcb, M, FCN, HD);
    }
    // out_proj + tanh
    {
        dim3 grid((NOUTC + 127) / 128, M / 128);
        gemm_bias_act<2><<<grid, 256>>>(fcb, out_w, out_b, (float*)d_out, M, NOUTC, FCN);
    }
}

// round 7
// speedup vs baseline: 1.4123x; 1.1397x over previous
#include <cuda_runtime.h>
#include <cuda_bf16.h>
#include <math.h>

// Problem constants
#define BSZ   32
#define TLEN  1024
#define DIN   768
#define HD    768
#define G3    2304          // 3*HD
#define FCN   512
#define NOUTC 39

typedef unsigned long long ull;

// ---------------------------------------------------------------------------
// Scratch (device globals; no allocation allowed)
// ---------------------------------------------------------------------------
__device__ float g_xproj[(size_t)BSZ * TLEN * G3];   // input projections [B,T,3H]
__device__ float g_hall [(size_t)BSZ * TLEN * HD];   // GRU outputs [B,T,H]
__device__ float g_fc   [(size_t)BSZ * TLEN * FCN];  // fc output
__device__ float g_hcur [2 * BSZ * HD];              // compact h double buffer

// Grid-barrier flags: monotonic, never reset -> equal at launch boundaries.
__device__ unsigned g_flags[96];

// ---------------------------------------------------------------------------
// Packed fp32x2 FMA helpers (feed-forward GEMM)
// ---------------------------------------------------------------------------
__device__ __forceinline__ void fma2(ull& d, ull a, ull b) {
    asm("fma.rn.f32x2 %0, %1, %2, %0;" : "+l"(d) : "l"(a), "l"(b));
}
__device__ __forceinline__ ull pack2(float lo, float hi) {
    ull d;
    asm("mov.b64 %0, {%1, %2};" : "=l"(d) : "f"(lo), "f"(hi));
    return d;
}
__device__ __forceinline__ float2 unpack2(ull v) {
    float2 r;
    asm("mov.b64 {%0, %1}, %2;" : "=f"(r.x), "=f"(r.y) : "l"(v));
    return r;
}

// bf16 pack helpers
__device__ __forceinline__ unsigned bfpk(float hi_src, float lo_src) {
    unsigned r;
    asm("cvt.rn.bf16x2.f32 %0, %1, %2;" : "=r"(r) : "f"(hi_src), "f"(lo_src));
    return r;
}
__device__ __forceinline__ float bflo(unsigned p) { return __uint_as_float(p << 16); }
__device__ __forceinline__ float bfhi(unsigned p) { return __uint_as_float(p & 0xFFFF0000u); }

// warp-level mma + ldmatrix (portable PTX, sm_80+)
__device__ __forceinline__ void mma16816(float* d, const unsigned* a,
                                         const unsigned* b) {
    asm volatile(
        "mma.sync.aligned.m16n8k16.row.col.f32.bf16.bf16.f32 "
        "{%0,%1,%2,%3}, {%4,%5,%6,%7}, {%8,%9}, {%0,%1,%2,%3};"
        : "+f"(d[0]), "+f"(d[1]), "+f"(d[2]), "+f"(d[3])
        : "r"(a[0]), "r"(a[1]), "r"(a[2]), "r"(a[3]), "r"(b[0]), "r"(b[1]));
}
__device__ __forceinline__ void ldmx4(unsigned* r, unsigned saddr) {
    asm volatile("ldmatrix.sync.aligned.m8n8.x4.shared.b16 {%0,%1,%2,%3}, [%4];"
                 : "=r"(r[0]), "=r"(r[1]), "=r"(r[2]), "=r"(r[3]) : "r"(saddr));
}
__device__ __forceinline__ void ldmx2(unsigned* r, unsigned saddr) {
    asm volatile("ldmatrix.sync.aligned.m8n8.x2.shared.b16 {%0,%1}, [%2];"
                 : "=r"(r[0]), "=r"(r[1]) : "r"(saddr));
}

// ---------------------------------------------------------------------------
// Generic fp32 GEMM (unchanged, passing since R3)
// ---------------------------------------------------------------------------
template <int ACT>
__global__ __launch_bounds__(256) void gemm_bias_act(
    const float* __restrict__ A, const float* __restrict__ W,
    const float* __restrict__ bias, float* __restrict__ C,
    int M, int N, int K)
{
    __shared__ float As[8][128];
    __shared__ float Bs[8][128];

    const int tid  = threadIdx.x;
    const int m0   = blockIdx.y * 128;
    const int n0   = blockIdx.x * 128;
    const int lrow = tid >> 1;
    const int lk4  = (tid & 1) * 4;
    const int tx = tid & 15;
    const int ty = tid >> 4;

    ull acc2[8][4];
#pragma unroll
    for (int i = 0; i < 8; i++)
#pragma unroll
        for (int j = 0; j < 4; j++) acc2[i][j] = 0ull;

    const float* Arow = A + (size_t)(m0 + lrow) * K + lk4;
    const float* Wrow = W + (size_t)(n0 + lrow) * K + lk4;
    const bool   wok  = (n0 + lrow) < N;

    for (int k0 = 0; k0 < K; k0 += 8) {
        float4 av = *(const float4*)(Arow + k0);
        float4 wv = make_float4(0.f, 0.f, 0.f, 0.f);
        if (wok) wv = *(const float4*)(Wrow + k0);

        __syncthreads();
        As[lk4 + 0][lrow] = av.x; As[lk4 + 1][lrow] = av.y;
        As[lk4 + 2][lrow] = av.z; As[lk4 + 3][lrow] = av.w;
        Bs[lk4 + 0][lrow] = wv.x; Bs[lk4 + 1][lrow] = wv.y;
        Bs[lk4 + 2][lrow] = wv.z; Bs[lk4 + 3][lrow] = wv.w;
        __syncthreads();

#pragma unroll
        for (int kk = 0; kk < 8; kk++) {
            float a[8];
            *(float4*)(a)     = *(const float4*)&As[kk][ty * 4];
            *(float4*)(a + 4) = *(const float4*)&As[kk][64 + ty * 4];
            ulonglong2 b01 = *(const ulonglong2*)&Bs[kk][tx * 4];
            ulonglong2 b23 = *(const ulonglong2*)&Bs[kk][64 + tx * 4];
            ull bb[4] = { b01.x, b01.y, b23.x, b23.y };
            ull aa[8];
#pragma unroll
            for (int i = 0; i < 8; i++) aa[i] = pack2(a[i], a[i]);
#pragma unroll
            for (int i = 0; i < 8; i++)
#pragma unroll
                for (int j = 0; j < 4; j++)
                    fma2(acc2[i][j], aa[i], bb[j]);
        }
    }

    const float selu_scale = 1.0507009873554804934193349852946f;
    const float selu_alpha = 1.6732632423543772848170429916717f;

#pragma unroll
    for (int i = 0; i < 8; i++) {
        const int m = m0 + ((i < 4) ? (ty * 4 + i) : (64 + ty * 4 + i - 4));
        float* crow = C + (size_t)m * N;
#pragma unroll
        for (int j = 0; j < 4; j++) {
            const int nf = n0 + ((j < 2) ? (tx * 4 + j * 2)
                                         : (64 + tx * 4 + (j - 2) * 2));
            float2 v = unpack2(acc2[i][j]);
            float vals[2] = { v.x, v.y };
#pragma unroll
            for (int s = 0; s < 2; s++) {
                const int n = nf + s;
                if (n < N) {
                    float val = vals[s] + bias[n];
                    if (ACT == 1) {
                        val = selu_scale * (val > 0.f ? val
                                                      : selu_alpha * (expf(val) - 1.f));
                    } else if (ACT == 2) {
                        val = tanhf(val);
                    }
                    crow[n] = val;
                }
            }
        }
    }
}

// ---------------------------------------------------------------------------
// Persistent GRU layer using warp-level mma.sync (split-bf16, 3 passes).
// 96 blocks x 256 threads (8 warps). Block owns 8 hidden units (24 gh rows).
// Warp w owns k-slice [96w, 96w+96). w fragments persist in registers.
// ---------------------------------------------------------------------------
#define NBLK    96
#define HPB     1552                         // bf16 row pitch in bytes (776 elems)
#define OFF_HHI 0                            // 32 x 1552 = 49664
#define OFF_HLO 49664
#define OFF_WHI 99328                        // 24 x 1552 = 37248
#define OFF_WLO 136576
#define OFF_PRT 173824                       // 8*768 f32 = 24576
#define MMA_SMEM (OFF_PRT + 24576)           // 198400 B

__global__ __launch_bounds__(256) void gru_layer_wmma(
    const float* __restrict__ xproj,   // [B,T,3H] (gi, b_ih folded in)
    const float* __restrict__ w_hh,    // [3H, H]
    const float* __restrict__ b_hh,    // [3H]
    float* __restrict__ h_all,         // [B,T,H]
    float* __restrict__ h_cur)         // [2][B*H]
{
    extern __shared__ char smc[];
    unsigned sbase;
    asm("{ .reg .u64 t; cvta.to.shared.u64 t, %1; cvt.u32.u64 %0, t; }"
        : "=r"(sbase) : "l"(smc));

    const int tid  = threadIdx.x;
    const int warp = tid >> 5;
    const int lane = tid & 31;
    const int u0   = blockIdx.x * 8;
    const unsigned flag_base = g_flags[blockIdx.x];

    // ---- one-time: convert w slice (24x768) to bf16 hi/lo in smem ----
    if (tid < 192) {
        const int n = tid % 24;              // gh row: gate = n>>3, unit = n&7
        const int c = tid / 24;              // k chunk (96 floats)
        const float* ws = w_hh + (size_t)((n >> 3) * HD + u0 + (n & 7)) * HD + c * 96;
#pragma unroll
        for (int j = 0; j < 12; j++) {
            float4 a = *(const float4*)(ws + j * 8);
            float4 b = *(const float4*)(ws + j * 8 + 4);
            unsigned h0 = bfpk(a.y, a.x), h1 = bfpk(a.w, a.z);
            unsigned h2 = bfpk(b.y, b.x), h3 = bfpk(b.w, b.z);
            unsigned l0 = bfpk(a.y - bfhi(h0), a.x - bflo(h0));
            unsigned l1 = bfpk(a.w - bfhi(h1), a.z - bflo(h1));
            unsigned l2 = bfpk(b.y - bfhi(h2), b.x - bflo(h2));
            unsigned l3 = bfpk(b.w - bfhi(h3), b.z - bflo(h3));
            const int off = n * HPB + (c * 96 + j * 8) * 2;
            *(uint4*)(smc + OFF_WHI + off) = make_uint4(h0, h1, h2, h3);
            *(uint4*)(smc + OFF_WLO + off) = make_uint4(l0, l1, l2, l3);
        }
    }
    __syncthreads();

    // ---- one-time: load persistent B fragments (w) for this warp's k ----
    unsigned bh[3][6][2], bl[3][6][2];
    {
        const int l2 = lane & 15;
#pragma unroll
        for (int nt = 0; nt < 3; nt++)
#pragma unroll
            for (int kt = 0; kt < 6; kt++) {
                const int row = nt * 8 + (l2 & 7);
                const int kel = warp * 96 + kt * 16 + ((l2 >> 3) & 1) * 8;
                ldmx2(bh[nt][kt], sbase + OFF_WHI + row * HPB + kel * 2);
                ldmx2(bl[nt][kt], sbase + OFF_WLO + row * HPB + kel * 2);
            }
    }
    __syncthreads();

    // ---- gate-phase decode ----
    const int bg = tid >> 3;          // batch 0..31
    const int ug = tid & 7;           // unit 0..7
    const float bias_r = b_hh[u0 + ug];
    const float bias_z = b_hh[HD + u0 + ug];
    const float bias_n = b_hh[2 * HD + u0 + ug];
    float hprev = 0.f;

    // ---- t = 0: gh = b_hh only ----
    {
        const size_t xb = ((size_t)bg * TLEN + 0) * G3 + (u0 + ug);
        const float gi_r = xproj[xb];
        const float gi_z = xproj[xb + HD];
        const float gi_n = xproj[xb + 2 * HD];
        const float r = 1.f / (1.f + expf(-(gi_r + bias_r)));
        const float z = 1.f / (1.f + expf(-(gi_z + bias_z)));
        const float n = tanhf(gi_n + r * bias_n);
        hprev = (1.f - z) * n;
        h_all[((size_t)bg * TLEN + 0) * HD + (u0 + ug)] = hprev;
        h_cur[(size_t)bg * HD + (u0 + ug)] = hprev;        // slot 0
        __syncthreads();
        if (tid == 0)
            asm volatile("st.release.gpu.global.u32 [%0], %1;"
                         :: "l"(&g_flags[blockIdx.x]), "r"(flag_base + 1u) : "memory");
    }

    float* prt = (float*)(smc + OFF_PRT);

    for (int t = 1; t < TLEN; t++) {
        // --- wait for all blocks' h_{t-1} ---
        const unsigned need = flag_base + (unsigned)t;
        if (tid < NBLK) {
            unsigned v;
            do {
                asm volatile("ld.acquire.gpu.global.u32 %0, [%1];"
                             : "=r"(v) : "l"(&g_flags[tid]) : "memory");
            } while ((int)(v - need) < 0);
        }
        __syncthreads();

        // gate-input prefetch (latency hidden under convert + mma)
        const size_t xb = ((size_t)bg * TLEN + t) * G3 + (u0 + ug);
        const float gi_r = xproj[xb];
        const float gi_z = xproj[xb + HD];
        const float gi_n = xproj[xb + 2 * HD];

        // --- convert h_{t-1}: warp w handles all 32 rows, k in [96w,96w+96) ---
        {
            const float* src = h_cur + (size_t)((t - 1) & 1) * (BSZ * HD)
                             + (size_t)lane * HD + warp * 96;
#pragma unroll
            for (int j = 0; j < 12; j++) {
                float4 a = __ldcg((const float4*)(src + j * 8));
                float4 b = __ldcg((const float4*)(src + j * 8 + 4));
                unsigned h0 = bfpk(a.y, a.x), h1 = bfpk(a.w, a.z);
                unsigned h2 = bfpk(b.y, b.x), h3 = bfpk(b.w, b.z);
                unsigned l0 = bfpk(a.y - bfhi(h0), a.x - bflo(h0));
                unsigned l1 = bfpk(a.w - bfhi(h1), a.z - bflo(h1));
                unsigned l2 = bfpk(b.y - bfhi(h2), b.x - bflo(h2));
                unsigned l3 = bfpk(b.w - bfhi(h3), b.z - bflo(h3));
                const int off = lane * HPB + (warp * 96 + j * 8) * 2;
                *(uint4*)(smc + OFF_HHI + off) = make_uint4(h0, h1, h2, h3);
                *(uint4*)(smc + OFF_HLO + off) = make_uint4(l0, l1, l2, l3);
            }
        }
        __syncwarp();

        // --- mma: 6 k-tiles, 2 m-tiles x 3 n-tiles, 3 split passes ---
        float acc[2][3][4];
#pragma unroll
        for (int mt = 0; mt < 2; mt++)
#pragma unroll
            for (int nt = 0; nt < 3; nt++)
#pragma unroll
                for (int e = 0; e < 4; e++) acc[mt][nt][e] = 0.f;

        const int q = lane >> 3;                  // ldmatrix quad
        const int rq = (q & 1) * 8 + (lane & 7);  // row within 16-row tile
#pragma unroll
        for (int kt = 0; kt < 6; kt++) {
            const int kel = warp * 96 + kt * 16 + (q >> 1) * 8;
            unsigned ah[2][4], al[2][4];
#pragma unroll
            for (int mt = 0; mt < 2; mt++) {
                const int row = mt * 16 + rq;
                ldmx4(ah[mt], sbase + OFF_HHI + row * HPB + kel * 2);
                ldmx4(al[mt], sbase + OFF_HLO + row * HPB + kel * 2);
            }
#pragma unroll
            for (int mt = 0; mt < 2; mt++)
#pragma unroll
                for (int nt = 0; nt < 3; nt++) {
                    mma16816(acc[mt][nt], ah[mt], bh[nt][kt]);
                    mma16816(acc[mt][nt], ah[mt], bl[nt][kt]);
                    mma16816(acc[mt][nt], al[mt], bh[nt][kt]);
                }
        }

        // --- dump partials: prt[warp*768 + row*24 + col] ---
        {
            float* wp = prt + warp * 768;
            const int r0 = lane >> 2;
            const int c0 = (lane & 3) * 2;
#pragma unroll
            for (int mt = 0; mt < 2; mt++)
#pragma unroll
                for (int nt = 0; nt < 3; nt++) {
                    const int base = (mt * 16 + r0) * 24 + nt * 8 + c0;
                    *(float2*)(wp + base)            = make_float2(acc[mt][nt][0], acc[mt][nt][1]);
                    *(float2*)(wp + base + 8 * 24)   = make_float2(acc[mt][nt][2], acc[mt][nt][3]);
                }
        }
        __syncthreads();

        // --- gates: one (batch, unit) per thread, sum 8 warp partials ---
        {
            float gh[3];
#pragma unroll
            for (int g = 0; g < 3; g++) {
                const int o = bg * 24 + g * 8 + ug;
                float s = 0.f;
#pragma unroll
                for (int w = 0; w < 8; w++) s += prt[w * 768 + o];
                gh[g] = s;
            }
            const float r = 1.f / (1.f + expf(-(gi_r + gh[0] + bias_r)));
            const float z = 1.f / (1.f + expf(-(gi_z + gh[1] + bias_z)));
            const float n = tanhf(gi_n + r * (gh[2] + bias_n));
            const float hnew = (1.f - z) * n + z * hprev;
            hprev = hnew;
            h_all[((size_t)bg * TLEN + t) * HD + (u0 + ug)] = hnew;
            h_cur[(size_t)(t & 1) * (BSZ * HD) + (size_t)bg * HD + (u0 + ug)] = hnew;
        }
        __syncthreads();

        if (tid == 0)
            asm volatile("st.release.gpu.global.u32 [%0], %1;"
                         :: "l"(&g_flags[blockIdx.x]),
                            "r"(flag_base + (unsigned)(t + 1)) : "memory");
    }
}

// ---------------------------------------------------------------------------
// Launch: 6 graph nodes.
// ---------------------------------------------------------------------------
extern "C" void kernel_launch(void* const* d_in, const int* in_sizes, int n_in,
                              void* d_out, int out_size)
{
    const float* features = (const float*)d_in[0];
    const float* w_ih0 = (const float*)d_in[2];
    const float* w_hh0 = (const float*)d_in[3];
    const float* b_ih0 = (const float*)d_in[4];
    const float* b_hh0 = (const float*)d_in[5];
    const float* w_ih1 = (const float*)d_in[6];
    const float* w_hh1 = (const float*)d_in[7];
    const float* b_ih1 = (const float*)d_in[8];
    const float* b_hh1 = (const float*)d_in[9];
    const float* fc_w  = (const float*)d_in[10];
    const float* fc_b  = (const float*)d_in[11];
    const float* out_w = (const float*)d_in[12];
    const float* out_b = (const float*)d_in[13];

    float *xproj, *hall, *fcb, *hcur;
    cudaGetSymbolAddress((void**)&xproj, g_xproj);
    cudaGetSymbolAddress((void**)&hall,  g_hall);
    cudaGetSymbolAddress((void**)&fcb,   g_fc);
    cudaGetSymbolAddress((void**)&hcur,  g_hcur);

    static bool attr_set = false;
    if (!attr_set) {
        cudaFuncSetAttribute(gru_layer_wmma,
                             cudaFuncAttributeMaxDynamicSharedMemorySize,
                             (int)MMA_SMEM);
        attr_set = true;
    }

    const int M = BSZ * TLEN;                 // 32768

    // Layer 0: input projection (b_ih folded in)
    {
        dim3 grid(G3 / 128, M / 128);
        gemm_bias_act<0><<<grid, 256>>>(features, w_ih0, b_ih0, xproj, M, G3, DIN);
    }
    gru_layer_wmma<<<NBLK, 256, MMA_SMEM>>>(xproj, w_hh0, b_hh0, hall, hcur);

    // Layer 1
    {
        dim3 grid(G3 / 128, M / 128);
        gemm_bias_act<0><<<grid, 256>>>(hall, w_ih1, b_ih1, xproj, M, G3, HD);
    }
    gru_layer_wmma<<<NBLK, 256, MMA_SMEM>>>(xproj, w_hh1, b_hh1, hall, hcur);

    // fc + SELU
    {
        dim3 grid(FCN / 128, M / 128);
        gemm_bias_act<1><<<grid, 256>>>(hall, fc_w, fc_b, fcb, M, FCN, HD);
    }
    // out_proj + tanh
    {
        dim3 grid((NOUTC + 127) / 128, M / 128);
        gemm_bias_act<2><<<grid, 256>>>(fcb, out_w, out_b, (float*)d_out, M, NOUTC, FCN);
    }
}

// round 8
// speedup vs baseline: 1.8143x; 1.2846x over previous
#include <cuda_runtime.h>
#include <cuda_bf16.h>
#include <math.h>

// Problem constants
#define BSZ   32
#define TLEN  1024
#define DIN   768
#define HD    768
#define G3    2304          // 3*HD
#define FCN   512
#define NOUTC 39

typedef unsigned long long ull;

// ---------------------------------------------------------------------------
// Scratch (device globals; no allocation allowed)
// ---------------------------------------------------------------------------
__device__ float g_xproj[(size_t)BSZ * TLEN * G3];   // input projections [B,T,3H]
__device__ float g_fc   [(size_t)BSZ * TLEN * FCN];  // fc output

// bf16 hi/lo planes
__device__ unsigned short g_fh [(size_t)BSZ * TLEN * DIN];   // features hi
__device__ unsigned short g_fl [(size_t)BSZ * TLEN * DIN];   // features lo
__device__ unsigned short g_hhi[(size_t)BSZ * TLEN * HD];    // h hi (layer0 then layer1)
__device__ unsigned short g_hlo[(size_t)BSZ * TLEN * HD];    // h lo
__device__ unsigned short g_w0h[(size_t)G3 * DIN], g_w0l[(size_t)G3 * DIN];
__device__ unsigned short g_w1h[(size_t)G3 * HD],  g_w1l[(size_t)G3 * HD];
__device__ unsigned short g_fwh[(size_t)FCN * HD], g_fwl[(size_t)FCN * HD];

// Grid-barrier flags: monotonic, never reset; padded to 128B lines.
__device__ unsigned g_flags[96 * 32];

// ---------------------------------------------------------------------------
// Helpers
// ---------------------------------------------------------------------------
__device__ __forceinline__ void fma2(ull& d, ull a, ull b) {
    asm("fma.rn.f32x2 %0, %1, %2, %0;" : "+l"(d) : "l"(a), "l"(b));
}
__device__ __forceinline__ ull pack2(float lo, float hi) {
    ull d; asm("mov.b64 %0, {%1, %2};" : "=l"(d) : "f"(lo), "f"(hi)); return d;
}
__device__ __forceinline__ float2 unpack2(ull v) {
    float2 r; asm("mov.b64 {%0, %1}, %2;" : "=f"(r.x), "=f"(r.y) : "l"(v)); return r;
}
__device__ __forceinline__ unsigned bfpk(float hi_src, float lo_src) {
    unsigned r;
    asm("cvt.rn.bf16x2.f32 %0, %1, %2;" : "=r"(r) : "f"(hi_src), "f"(lo_src));
    return r;
}
__device__ __forceinline__ float bflo(unsigned p) { return __uint_as_float(p << 16); }
__device__ __forceinline__ float bfhi(unsigned p) { return __uint_as_float(p & 0xFFFF0000u); }

__device__ __forceinline__ void mma16816(float* d, const unsigned* a,
                                         const unsigned* b) {
    asm volatile(
        "mma.sync.aligned.m16n8k16.row.col.f32.bf16.bf16.f32 "
        "{%0,%1,%2,%3}, {%4,%5,%6,%7}, {%8,%9}, {%0,%1,%2,%3};"
        : "+f"(d[0]), "+f"(d[1]), "+f"(d[2]), "+f"(d[3])
        : "r"(a[0]), "r"(a[1]), "r"(a[2]), "r"(a[3]), "r"(b[0]), "r"(b[1]));
}
__device__ __forceinline__ void ldmx4(unsigned* r, unsigned saddr) {
    asm volatile("ldmatrix.sync.aligned.m8n8.x4.shared.b16 {%0,%1,%2,%3}, [%4];"
                 : "=r"(r[0]), "=r"(r[1]), "=r"(r[2]), "=r"(r[3]) : "r"(saddr));
}
__device__ __forceinline__ void ldmx2(unsigned* r, unsigned saddr) {
    asm volatile("ldmatrix.sync.aligned.m8n8.x2.shared.b16 {%0,%1}, [%2];"
                 : "=r"(r[0]), "=r"(r[1]) : "r"(saddr));
}
__device__ __forceinline__ void cp16(void* smem_dst, const void* gsrc) {
    unsigned s = (unsigned)__cvta_generic_to_shared(smem_dst);
    asm volatile("cp.async.cg.shared.global [%0], [%1], 16;" :: "r"(s), "l"(gsrc));
}
__device__ __forceinline__ void cp_commit() { asm volatile("cp.async.commit_group;"); }
template <int N>
__device__ __forceinline__ void cp_wait() {
    asm volatile("cp.async.wait_group %0;" :: "n"(N));
}

// ---------------------------------------------------------------------------
// Prep: fp32 -> bf16 hi/lo planes (elementwise, float4 granularity)
// ---------------------------------------------------------------------------
__global__ __launch_bounds__(256) void pack_hl(
    const float* __restrict__ src,
    unsigned short* __restrict__ dhi, unsigned short* __restrict__ dlo, int n4)
{
    const int i = blockIdx.x * 256 + threadIdx.x;
    if (i >= n4) return;
    float4 v = ((const float4*)src)[i];
    unsigned p0 = bfpk(v.x, v.x), p1 = bfpk(v.y, v.y);
    unsigned p2 = bfpk(v.z, v.z), p3 = bfpk(v.w, v.w);
    float r0 = v.x - bflo(p0), r1 = v.y - bflo(p1);
    float r2 = v.z - bflo(p2), r3 = v.w - bflo(p3);
    unsigned q0 = bfpk(r0, r0), q1 = bfpk(r1, r1);
    unsigned q2 = bfpk(r2, r2), q3 = bfpk(r3, r3);
    ushort4 hi, lo;
    hi.x = (unsigned short)p0; hi.y = (unsigned short)p1;
    hi.z = (unsigned short)p2; hi.w = (unsigned short)p3;
    lo.x = (unsigned short)q0; lo.y = (unsigned short)q1;
    lo.z = (unsigned short)q2; lo.w = (unsigned short)q3;
    ((ushort4*)dhi)[i] = hi;
    ((ushort4*)dlo)[i] = lo;
}

// ---------------------------------------------------------------------------
// Split-bf16 tensor GEMM: C[M,N] = act(A@W^T + bias), A/W as hi/lo planes.
// BM=128, BN=64, BK=64, 256 threads (8 warps: 4m x 2n), 3-pass split.
// smem: double-buffered, odd pitch 144B -> conflict-free STS/ldmatrix.
// ACT: 0 none, 1 SELU.
// ---------------------------------------------------------------------------
#define GP      144                           // smem row pitch (bytes)
#define SA_HI   0
#define SA_LO   (128 * GP)                    // 18432
#define SW_HI   (2 * 128 * GP)                // 36864
#define SW_LO   (SW_HI + 64 * GP)             // 46080
#define STAGE   (SW_LO + 64 * GP)             // 55296
#define GSMEM   (2 * STAGE)                   // 110592

template <int ACT>
__global__ __launch_bounds__(256) void gemm_bf16_hl(
    const unsigned short* __restrict__ Ah, const unsigned short* __restrict__ Al,
    const unsigned short* __restrict__ Wh, const unsigned short* __restrict__ Wl,
    const float* __restrict__ bias, float* __restrict__ C,
    int M, int N, int K)
{
    extern __shared__ char smg[];
    unsigned sbase;
    asm("{ .reg .u64 t; cvta.to.shared.u64 t, %1; cvt.u32.u64 %0, t; }"
        : "=r"(sbase) : "l"(smg));

    const int tid  = threadIdx.x;
    const int warp = tid >> 5;
    const int lane = tid & 31;
    const int wm   = warp >> 1;          // 0..3
    const int wn   = warp & 1;           // 0..1
    const int m0   = blockIdx.y * 128;
    const int n0   = blockIdx.x * 64;

    const int lr = tid >> 3;             // 0..31
    const int lc = tid & 7;              // 0..7 (16B chunk)

    const int NS = K / 64;

    // slab loader
    auto load_slab = [&](int s) {
        const int k0 = s * 64;
        char* st = smg + (s & 1) * STAGE;
#pragma unroll
        for (int p = 0; p < 4; p++) {
            const int r = lr + p * 32;
            cp16(st + SA_HI + r * GP + lc * 16, Ah + (size_t)(m0 + r) * K + k0 + lc * 8);
            cp16(st + SA_LO + r * GP + lc * 16, Al + (size_t)(m0 + r) * K + k0 + lc * 8);
        }
#pragma unroll
        for (int p = 0; p < 2; p++) {
            const int r = lr + p * 32;
            cp16(st + SW_HI + r * GP + lc * 16, Wh + (size_t)(n0 + r) * K + k0 + lc * 8);
            cp16(st + SW_LO + r * GP + lc * 16, Wl + (size_t)(n0 + r) * K + k0 + lc * 8);
        }
        cp_commit();
    };

    float acc[2][4][4];
#pragma unroll
    for (int mt = 0; mt < 2; mt++)
#pragma unroll
        for (int nt = 0; nt < 4; nt++)
#pragma unroll
            for (int e = 0; e < 4; e++) acc[mt][nt][e] = 0.f;

    const int q  = lane >> 3;
    const int rq = (q & 1) * 8 + (lane & 7);
    const int qk = q >> 1;
    const int l2 = lane & 15;
    const int brow = l2 & 7;
    const int bk16 = ((l2 >> 3) & 1) * 16;    // byte offset for B k-half

    load_slab(0);

    for (int s = 0; s < NS; s++) {
        if (s + 1 < NS) { load_slab(s + 1); cp_wait<1>(); }
        else           { cp_wait<0>(); }
        __syncthreads();

        const unsigned stA_hi = sbase + (s & 1) * STAGE + SA_HI;
        const unsigned stA_lo = sbase + (s & 1) * STAGE + SA_LO;
        const unsigned stW_hi = sbase + (s & 1) * STAGE + SW_HI;
        const unsigned stW_lo = sbase + (s & 1) * STAGE + SW_LO;

#pragma unroll
        for (int kt = 0; kt < 4; kt++) {
            unsigned ah[2][4], al[2][4], bh2[4][2], bl2[4][2];
#pragma unroll
            for (int mt = 0; mt < 2; mt++) {
                const int row = wm * 32 + mt * 16 + rq;
                ldmx4(ah[mt], stA_hi + row * GP + kt * 32 + qk * 16);
                ldmx4(al[mt], stA_lo + row * GP + kt * 32 + qk * 16);
            }
#pragma unroll
            for (int nt = 0; nt < 4; nt++) {
                const int row = wn * 32 + nt * 8 + brow;
                ldmx2(bh2[nt], stW_hi + row * GP + kt * 32 + bk16);
                ldmx2(bl2[nt], stW_lo + row * GP + kt * 32 + bk16);
            }
#pragma unroll
            for (int mt = 0; mt < 2; mt++)
#pragma unroll
                for (int nt = 0; nt < 4; nt++) {
                    mma16816(acc[mt][nt], ah[mt], bh2[nt]);
                    mma16816(acc[mt][nt], ah[mt], bl2[nt]);
                    mma16816(acc[mt][nt], al[mt], bh2[nt]);
                }
        }
        __syncthreads();
    }

    // epilogue
    const float selu_scale = 1.0507009873554804934193349852946f;
    const float selu_alpha = 1.6732632423543772848170429916717f;
    const int r0 = lane >> 2;
    const int c0 = (lane & 3) * 2;
#pragma unroll
    for (int mt = 0; mt < 2; mt++)
#pragma unroll
        for (int nt = 0; nt < 4; nt++) {
            const int col = n0 + wn * 32 + nt * 8 + c0;
            const float b0 = bias[col], b1 = bias[col + 1];
#pragma unroll
            for (int h = 0; h < 2; h++) {
                const int row = m0 + wm * 32 + mt * 16 + r0 + h * 8;
                float v0 = acc[mt][nt][h * 2 + 0] + b0;
                float v1 = acc[mt][nt][h * 2 + 1] + b1;
                if (ACT == 1) {
                    v0 = selu_scale * (v0 > 0.f ? v0 : selu_alpha * (expf(v0) - 1.f));
                    v1 = selu_scale * (v1 > 0.f ? v1 : selu_alpha * (expf(v1) - 1.f));
                }
                *(float2*)(C + (size_t)row * N + col) = make_float2(v0, v1);
            }
        }
}

// ---------------------------------------------------------------------------
// FFMA2 GEMM (kept for out_proj, N=39): C = tanh(A@W^T + b)
// ---------------------------------------------------------------------------
__global__ __launch_bounds__(256) void gemm_out_tanh(
    const float* __restrict__ A, const float* __restrict__ W,
    const float* __restrict__ bias, float* __restrict__ C,
    int M, int N, int K)
{
    __shared__ float As[8][128];
    __shared__ float Bs[8][128];

    const int tid  = threadIdx.x;
    const int m0   = blockIdx.y * 128;
    const int n0   = 0;
    const int lrow = tid >> 1;
    const int lk4  = (tid & 1) * 4;
    const int tx = tid & 15;
    const int ty = tid >> 4;

    ull acc2[8][4];
#pragma unroll
    for (int i = 0; i < 8; i++)
#pragma unroll
        for (int j = 0; j < 4; j++) acc2[i][j] = 0ull;

    const float* Arow = A + (size_t)(m0 + lrow) * K + lk4;
    const float* Wrow = W + (size_t)(n0 + lrow) * K + lk4;
    const bool   wok  = (n0 + lrow) < N;

    for (int k0 = 0; k0 < K; k0 += 8) {
        float4 av = *(const float4*)(Arow + k0);
        float4 wv = make_float4(0.f, 0.f, 0.f, 0.f);
        if (wok) wv = *(const float4*)(Wrow + k0);

        __syncthreads();
        As[lk4 + 0][lrow] = av.x; As[lk4 + 1][lrow] = av.y;
        As[lk4 + 2][lrow] = av.z; As[lk4 + 3][lrow] = av.w;
        Bs[lk4 + 0][lrow] = wv.x; Bs[lk4 + 1][lrow] = wv.y;
        Bs[lk4 + 2][lrow] = wv.z; Bs[lk4 + 3][lrow] = wv.w;
        __syncthreads();

#pragma unroll
        for (int kk = 0; kk < 8; kk++) {
            float a[8];
            *(float4*)(a)     = *(const float4*)&As[kk][ty * 4];
            *(float4*)(a + 4) = *(const float4*)&As[kk][64 + ty * 4];
            ulonglong2 b01 = *(const ulonglong2*)&Bs[kk][tx * 4];
            ulonglong2 b23 = *(const ulonglong2*)&Bs[kk][64 + tx * 4];
            ull bb[4] = { b01.x, b01.y, b23.x, b23.y };
            ull aa[8];
#pragma unroll
            for (int i = 0; i < 8; i++) aa[i] = pack2(a[i], a[i]);
#pragma unroll
            for (int i = 0; i < 8; i++)
#pragma unroll
                for (int j = 0; j < 4; j++)
                    fma2(acc2[i][j], aa[i], bb[j]);
        }
    }

#pragma unroll
    for (int i = 0; i < 8; i++) {
        const int m = m0 + ((i < 4) ? (ty * 4 + i) : (64 + ty * 4 + i - 4));
        float* crow = C + (size_t)m * N;
#pragma unroll
        for (int j = 0; j < 4; j++) {
            const int nf = n0 + ((j < 2) ? (tx * 4 + j * 2)
                                         : (64 + tx * 4 + (j - 2) * 2));
            float2 v = unpack2(acc2[i][j]);
            float vals[2] = { v.x, v.y };
#pragma unroll
            for (int s = 0; s < 2; s++) {
                const int n = nf + s;
                if (n < N) crow[n] = tanhf(vals[s] + bias[n]);
            }
        }
    }
}

// ---------------------------------------------------------------------------
// Persistent GRU layer, warp-granular dataflow + bf16-plane h.
// 96 blocks x 256 threads. Block owns 8 units (24 gh rows).
// Warp w: polls 12 source-block flags, copies its k-slice of h planes into
// smem, ldmatrix+mma (108 mma, persistent B frags), dump partials.
// Then block-wide: gates, pack h_t to planes, release flag.
// ---------------------------------------------------------------------------
#define NBLK    96
#define HPB     1552                         // bf16 row pitch (bytes)
#define OFF_HHI 0                            // 32 x 1552 = 49664
#define OFF_HLO 49664
#define OFF_WHI 99328                        // 24 x 1552 = 37248
#define OFF_WLO 136576
#define OFF_PRT 173824                       // 8*768 f32 = 24576
#define MMA_SMEM (OFF_PRT + 24576)           // 198400 B

__global__ __launch_bounds__(256) void gru_layer_wmma(
    const float* __restrict__ xproj,         // [B,T,3H] (gi, b_ih folded in)
    const float* __restrict__ w_hh,          // [3H, H] fp32
    const float* __restrict__ b_hh,          // [3H]
    unsigned short* __restrict__ hhi,        // [B,T,H] bf16-hi plane
    unsigned short* __restrict__ hlo)        // [B,T,H] bf16-lo plane
{
    extern __shared__ char smc[];
    unsigned sbase;
    asm("{ .reg .u64 t; cvta.to.shared.u64 t, %1; cvt.u32.u64 %0, t; }"
        : "=r"(sbase) : "l"(smc));

    const int tid  = threadIdx.x;
    const int warp = tid >> 5;
    const int lane = tid & 31;
    const int u0   = blockIdx.x * 8;
    const unsigned flag_base = g_flags[blockIdx.x * 32];

    // ---- one-time: convert w slice (24x768 fp32) to bf16 hi/lo smem ----
    if (tid < 192) {
        const int n = tid % 24;
        const int c = tid / 24;
        const float* ws = w_hh + (size_t)((n >> 3) * HD + u0 + (n & 7)) * HD + c * 96;
#pragma unroll
        for (int j = 0; j < 12; j++) {
            float4 a = *(const float4*)(ws + j * 8);
            float4 b = *(const float4*)(ws + j * 8 + 4);
            unsigned h0 = bfpk(a.y, a.x), h1 = bfpk(a.w, a.z);
            unsigned h2 = bfpk(b.y, b.x), h3 = bfpk(b.w, b.z);
            unsigned l0 = bfpk(a.y - bfhi(h0), a.x - bflo(h0));
            unsigned l1 = bfpk(a.w - bfhi(h1), a.z - bflo(h1));
            unsigned l2 = bfpk(b.y - bfhi(h2), b.x - bflo(h2));
            unsigned l3 = bfpk(b.w - bfhi(h3), b.z - bflo(h3));
            const int off = n * HPB + (c * 96 + j * 8) * 2;
            *(uint4*)(smc + OFF_WHI + off) = make_uint4(h0, h1, h2, h3);
            *(uint4*)(smc + OFF_WLO + off) = make_uint4(l0, l1, l2, l3);
        }
    }
    __syncthreads();

    // ---- one-time: persistent B fragments for this warp's k-slice ----
    unsigned bh[3][6][2], bl[3][6][2];
    {
        const int l2 = lane & 15;
#pragma unroll
        for (int nt = 0; nt < 3; nt++)
#pragma unroll
            for (int kt = 0; kt < 6; kt++) {
                const int row = nt * 8 + (l2 & 7);
                const int kel = warp * 96 + kt * 16 + ((l2 >> 3) & 1) * 8;
                ldmx2(bh[nt][kt], sbase + OFF_WHI + row * HPB + kel * 2);
                ldmx2(bl[nt][kt], sbase + OFF_WLO + row * HPB + kel * 2);
            }
    }
    __syncthreads();

    // ---- gate decode ----
    const int bg = tid >> 3;
    const int ug = tid & 7;
    const float bias_r = b_hh[u0 + ug];
    const float bias_z = b_hh[HD + u0 + ug];
    const float bias_n = b_hh[2 * HD + u0 + ug];
    float hprev = 0.f;

    // ---- t = 0: gh = b_hh only ----
    {
        const size_t xb = ((size_t)bg * TLEN + 0) * G3 + (u0 + ug);
        const float gi_r = xproj[xb];
        const float gi_z = xproj[xb + HD];
        const float gi_n = xproj[xb + 2 * HD];
        const float r = 1.f / (1.f + expf(-(gi_r + bias_r)));
        const float z = 1.f / (1.f + expf(-(gi_z + bias_z)));
        const float n = tanhf(gi_n + r * bias_n);
        hprev = (1.f - z) * n;
        const size_t hidx = ((size_t)bg * TLEN + 0) * HD + (u0 + ug);
        unsigned p = bfpk(hprev, hprev);
        float res = hprev - bflo(p);
        unsigned ql = bfpk(res, res);
        hhi[hidx] = (unsigned short)p;
        hlo[hidx] = (unsigned short)ql;
        __syncthreads();
        if (tid == 0)
            asm volatile("st.release.gpu.global.u32 [%0], %1;"
                         :: "l"(&g_flags[blockIdx.x * 32]), "r"(flag_base + 1u) : "memory");
    }

    float* prt = (float*)(smc + OFF_PRT);
    const int src0 = 12 * warp;               // first source block for this warp

    for (int t = 1; t < TLEN; t++) {
        // --- warp-granular wait: only the 12 blocks owning this k-slice ---
        const unsigned need = flag_base + (unsigned)t;
        if (lane < 12) {
            const unsigned* fp = &g_flags[(src0 + lane) * 32];
            unsigned v;
            do {
                asm volatile("ld.acquire.gpu.global.u32 %0, [%1];"
                             : "=r"(v) : "l"(fp) : "memory");
            } while ((int)(v - need) < 0);
        }
        __syncwarp();

        // gate-input prefetch (independent; hidden under copy + mma)
        const size_t xb = ((size_t)bg * TLEN + t) * G3 + (u0 + ug);
        const float gi_r = xproj[xb];
        const float gi_z = xproj[xb + HD];
        const float gi_n = xproj[xb + 2 * HD];

        // --- stage h_{t-1} slice: straight plane copy, no conversion ---
        {
            const size_t rb = ((size_t)lane * TLEN + (t - 1)) * HD + warp * 96;
            const unsigned short* sh = hhi + rb;
            const unsigned short* sl = hlo + rb;
            char* dh = smc + OFF_HHI + lane * HPB + (warp * 96) * 2;
            char* dl = smc + OFF_HLO + lane * HPB + (warp * 96) * 2;
#pragma unroll
            for (int j = 0; j < 12; j++) {
                uint4 vh = __ldcg((const uint4*)(sh + j * 8));
                uint4 vl = __ldcg((const uint4*)(sl + j * 8));
                *(uint4*)(dh + j * 16) = vh;
                *(uint4*)(dl + j * 16) = vl;
            }
        }
        __syncwarp();

        // --- mma: 6 k-tiles, 2 m x 3 n, 3 split passes ---
        float acc[2][3][4];
#pragma unroll
        for (int mt = 0; mt < 2; mt++)
#pragma unroll
            for (int nt = 0; nt < 3; nt++)
#pragma unroll
                for (int e = 0; e < 4; e++) acc[mt][nt][e] = 0.f;

        const int q = lane >> 3;
        const int rq = (q & 1) * 8 + (lane & 7);
#pragma unroll
        for (int kt = 0; kt < 6; kt++) {
            const int kel = warp * 96 + kt * 16 + (q >> 1) * 8;
            unsigned ah[2][4], al[2][4];
#pragma unroll
            for (int mt = 0; mt < 2; mt++) {
                const int row = mt * 16 + rq;
                ldmx4(ah[mt], sbase + OFF_HHI + row * HPB + kel * 2);
                ldmx4(al[mt], sbase + OFF_HLO + row * HPB + kel * 2);
            }
#pragma unroll
            for (int mt = 0; mt < 2; mt++)
#pragma unroll
                for (int nt = 0; nt < 3; nt++) {
                    mma16816(acc[mt][nt], ah[mt], bh[nt][kt]);
                    mma16816(acc[mt][nt], ah[mt], bl[nt][kt]);
                    mma16816(acc[mt][nt], al[mt], bh[nt][kt]);
                }
        }

        // --- dump partials ---
        {
            float* wp = prt + warp * 768;
            const int r0 = lane >> 2;
            const int c0 = (lane & 3) * 2;
#pragma unroll
            for (int mt = 0; mt < 2; mt++)
#pragma unroll
                for (int nt = 0; nt < 3; nt++) {
                    const int base = (mt * 16 + r0) * 24 + nt * 8 + c0;
                    *(float2*)(wp + base)          = make_float2(acc[mt][nt][0], acc[mt][nt][1]);
                    *(float2*)(wp + base + 8 * 24) = make_float2(acc[mt][nt][2], acc[mt][nt][3]);
                }
        }
        __syncthreads();

        // --- gates ---
        {
            float gh[3];
#pragma unroll
            for (int g = 0; g < 3; g++) {
                const int o = bg * 24 + g * 8 + ug;
                float s = 0.f;
#pragma unroll
                for (int w = 0; w < 8; w++) s += prt[w * 768 + o];
                gh[g] = s;
            }
            const float r = 1.f / (1.f + expf(-(gi_r + gh[0] + bias_r)));
            const float z = 1.f / (1.f + expf(-(gi_z + gh[1] + bias_z)));
            const float n = tanhf(gi_n + r * (gh[2] + bias_n));
            const float hnew = (1.f - z) * n + z * hprev;
            hprev = hnew;
            const size_t hidx = ((size_t)bg * TLEN + t) * HD + (u0 + ug);
            unsigned p = bfpk(hnew, hnew);
            float res = hnew - bflo(p);
            unsigned ql = bfpk(res, res);
            hhi[hidx] = (unsigned short)p;
            hlo[hidx] = (unsigned short)ql;
        }
        __syncthreads();   // all h stores issued; prt consumable next step

        if (tid == 0)
            asm volatile("st.release.gpu.global.u32 [%0], %1;"
                         :: "l"(&g_flags[blockIdx.x * 32]),
                            "r"(flag_base + (unsigned)(t + 1)) : "memory");
    }
}

// ---------------------------------------------------------------------------
// Launch: 10 graph nodes.
// ---------------------------------------------------------------------------
extern "C" void kernel_launch(void* const* d_in, const int* in_sizes, int n_in,
                              void* d_out, int out_size)
{
    const float* features = (const float*)d_in[0];
    const float* w_ih0 = (const float*)d_in[2];
    const float* w_hh0 = (const float*)d_in[3];
    const float* b_ih0 = (const float*)d_in[4];
    const float* b_hh0 = (const float*)d_in[5];
    const float* w_ih1 = (const float*)d_in[6];
    const float* w_hh1 = (const float*)d_in[7];
    const float* b_ih1 = (const float*)d_in[8];
    const float* b_hh1 = (const float*)d_in[9];
    const float* fc_w  = (const float*)d_in[10];
    const float* fc_b  = (const float*)d_in[11];
    const float* out_w = (const float*)d_in[12];
    const float* out_b = (const float*)d_in[13];

    float *xproj, *fcb;
    unsigned short *fh, *fl, *hhi, *hlo, *w0h, *w0l, *w1h, *w1l, *fwh, *fwl;
    cudaGetSymbolAddress((void**)&xproj, g_xproj);
    cudaGetSymbolAddress((void**)&fcb,   g_fc);
    cudaGetSymbolAddress((void**)&fh,  g_fh);
    cudaGetSymbolAddress((void**)&fl,  g_fl);
    cudaGetSymbolAddress((void**)&hhi, g_hhi);
    cudaGetSymbolAddress((void**)&hlo, g_hlo);
    cudaGetSymbolAddress((void**)&w0h, g_w0h);
    cudaGetSymbolAddress((void**)&w0l, g_w0l);
    cudaGetSymbolAddress((void**)&w1h, g_w1h);
    cudaGetSymbolAddress((void**)&w1l, g_w1l);
    cudaGetSymbolAddress((void**)&fwh, g_fwh);
    cudaGetSymbolAddress((void**)&fwl, g_fwl);

    static bool attr_set = false;
    if (!attr_set) {
        cudaFuncSetAttribute(gru_layer_wmma,
                             cudaFuncAttributeMaxDynamicSharedMemorySize, (int)MMA_SMEM);
        cudaFuncSetAttribute(gemm_bf16_hl<0>,
                             cudaFuncAttributeMaxDynamicSharedMemorySize, (int)GSMEM);
        cudaFuncSetAttribute(gemm_bf16_hl<1>,
                             cudaFuncAttributeMaxDynamicSharedMemorySize, (int)GSMEM);
        attr_set = true;
    }

    const int M = BSZ * TLEN;                 // 32768

    // Prep: pack fp32 -> bf16 hi/lo planes
    {
        int n4 = (BSZ * TLEN * DIN) / 4;      // features
        pack_hl<<<(n4 + 255) / 256, 256>>>(features, fh, fl, n4);
        n4 = (G3 * DIN) / 4;
        pack_hl<<<(n4 + 255) / 256, 256>>>(w_ih0, w0h, w0l, n4);
        n4 = (G3 * HD) / 4;
        pack_hl<<<(n4 + 255) / 256, 256>>>(w_ih1, w1h, w1l, n4);
        n4 = (FCN * HD) / 4;
        pack_hl<<<(n4 + 255) / 256, 256>>>(fc_w, fwh, fwl, n4);
    }

    // Layer 0: input projection (bias b_ih folded in)
    gemm_bf16_hl<0><<<dim3(G3 / 64, M / 128), 256, GSMEM>>>(
        fh, fl, w0h, w0l, b_ih0, xproj, M, G3, DIN);
    gru_layer_wmma<<<NBLK, 256, MMA_SMEM>>>(xproj, w_hh0, b_hh0, hhi, hlo);

    // Layer 1: input projection reads layer-0 h planes
    gemm_bf16_hl<0><<<dim3(G3 / 64, M / 128), 256, GSMEM>>>(
        hhi, hlo, w1h, w1l, b_ih1, xproj, M, G3, HD);
    gru_layer_wmma<<<NBLK, 256, MMA_SMEM>>>(xproj, w_hh1, b_hh1, hhi, hlo);

    // fc + SELU (reads layer-1 h planes)
    gemm_bf16_hl<1><<<dim3(FCN / 64, M / 128), 256, GSMEM>>>(
        hhi, hlo, fwh, fwl, fc_b, fcb, M, FCN, HD);

    // out_proj + tanh (fp32 FFMA2; N=39)
    gemm_out_tanh<<<dim3(1, M / 128), 256>>>(fcb, out_w, out_b, (float*)d_out,
                                             M, NOUTC, FCN);
}

// round 9
// speedup vs baseline: 3.4937x; 1.9257x over previous
#include <cuda_runtime.h>
#include <cuda_bf16.h>
#include <math.h>

// Problem constants
#define BSZ   32
#define TLEN  1024
#define DIN   768
#define HD    768
#define G3    2304
#define FCN   512
#define NOUTC 39

typedef unsigned long long ull;
typedef unsigned short u16;

// ---------------------------------------------------------------------------
// Scratch (device globals)
// ---------------------------------------------------------------------------
__device__ float g_xproj [(size_t)BSZ * TLEN * G3];   // layer-0 input projections
__device__ float g_xproj2[(size_t)BSZ * TLEN * G3];   // layer-1 input projections
__device__ float g_fc    [(size_t)BSZ * TLEN * FCN];  // fc output
__device__ float g_cb0[G3], g_cb1[G3];                // combined biases (b_ih + b_hh[r,z])

// bf16 hi/lo planes
__device__ u16 g_fh [(size_t)BSZ * TLEN * DIN], g_fl [(size_t)BSZ * TLEN * DIN];
__device__ u16 g_hhi[(size_t)BSZ * TLEN * HD],  g_hlo[(size_t)BSZ * TLEN * HD];
__device__ u16 g_w0h[(size_t)G3 * DIN], g_w0l[(size_t)G3 * DIN];
__device__ u16 g_w1h[(size_t)G3 * HD],  g_w1l[(size_t)G3 * HD];
__device__ u16 g_fwh[(size_t)FCN * HD], g_fwl[(size_t)FCN * HD];

// Flags: monotonic, +1024 per fused launch, padded to 128B lines.
__device__ unsigned g_flags[96 * 32];

// ---------------------------------------------------------------------------
// Helpers
// ---------------------------------------------------------------------------
__device__ __forceinline__ void fma2(ull& d, ull a, ull b) {
    asm("fma.rn.f32x2 %0, %1, %2, %0;" : "+l"(d) : "l"(a), "l"(b));
}
__device__ __forceinline__ ull pack2(float lo, float hi) {
    ull d; asm("mov.b64 %0, {%1, %2};" : "=l"(d) : "f"(lo), "f"(hi)); return d;
}
__device__ __forceinline__ float2 unpack2(ull v) {
    float2 r; asm("mov.b64 {%0, %1}, %2;" : "=f"(r.x), "=f"(r.y) : "l"(v)); return r;
}
__device__ __forceinline__ unsigned bfpk(float hi_src, float lo_src) {
    unsigned r;
    asm("cvt.rn.bf16x2.f32 %0, %1, %2;" : "=r"(r) : "f"(hi_src), "f"(lo_src));
    return r;
}
__device__ __forceinline__ float bflo(unsigned p) { return __uint_as_float(p << 16); }
__device__ __forceinline__ float bfhi(unsigned p) { return __uint_as_float(p & 0xFFFF0000u); }

__device__ __forceinline__ void mma16816(float* d, const unsigned* a, const unsigned* b) {
    asm volatile(
        "mma.sync.aligned.m16n8k16.row.col.f32.bf16.bf16.f32 "
        "{%0,%1,%2,%3}, {%4,%5,%6,%7}, {%8,%9}, {%0,%1,%2,%3};"
        : "+f"(d[0]), "+f"(d[1]), "+f"(d[2]), "+f"(d[3])
        : "r"(a[0]), "r"(a[1]), "r"(a[2]), "r"(a[3]), "r"(b[0]), "r"(b[1]));
}
__device__ __forceinline__ void ldmx4(unsigned* r, unsigned saddr) {
    asm volatile("ldmatrix.sync.aligned.m8n8.x4.shared.b16 {%0,%1,%2,%3}, [%4];"
                 : "=r"(r[0]), "=r"(r[1]), "=r"(r[2]), "=r"(r[3]) : "r"(saddr));
}
__device__ __forceinline__ void ldmx2(unsigned* r, unsigned saddr) {
    asm volatile("ldmatrix.sync.aligned.m8n8.x2.shared.b16 {%0,%1}, [%2];"
                 : "=r"(r[0]), "=r"(r[1]) : "r"(saddr));
}
__device__ __forceinline__ void cp16(void* smem_dst, const void* gsrc) {
    unsigned s = (unsigned)__cvta_generic_to_shared(smem_dst);
    asm volatile("cp.async.cg.shared.global [%0], [%1], 16;" :: "r"(s), "l"(gsrc));
}
__device__ __forceinline__ void cp_commit() { asm volatile("cp.async.commit_group;"); }
template <int N>
__device__ __forceinline__ void cp_wait() {
    asm volatile("cp.async.wait_group %0;" :: "n"(N));
}
__device__ __forceinline__ unsigned ld_acq(const unsigned* p) {
    unsigned v;
    asm volatile("ld.acquire.gpu.global.u32 %0, [%1];" : "=r"(v) : "l"(p) : "memory");
    return v;
}
__device__ __forceinline__ void st_rel(unsigned* p, unsigned v) {
    asm volatile("st.release.gpu.global.u32 [%0], %1;" :: "l"(p), "r"(v) : "memory");
}

// ---------------------------------------------------------------------------
// Prep kernels
// ---------------------------------------------------------------------------
__global__ __launch_bounds__(256) void pack_hl(
    const float* __restrict__ src, u16* __restrict__ dhi, u16* __restrict__ dlo, int n4)
{
    const int i = blockIdx.x * 256 + threadIdx.x;
    if (i >= n4) return;
    float4 v = ((const float4*)src)[i];
    unsigned p0 = bfpk(v.x, v.x), p1 = bfpk(v.y, v.y);
    unsigned p2 = bfpk(v.z, v.z), p3 = bfpk(v.w, v.w);
    float r0 = v.x - bflo(p0), r1 = v.y - bflo(p1);
    float r2 = v.z - bflo(p2), r3 = v.w - bflo(p3);
    unsigned q0 = bfpk(r0, r0), q1 = bfpk(r1, r1);
    unsigned q2 = bfpk(r2, r2), q3 = bfpk(r3, r3);
    ushort4 hi, lo;
    hi.x = (u16)p0; hi.y = (u16)p1; hi.z = (u16)p2; hi.w = (u16)p3;
    lo.x = (u16)q0; lo.y = (u16)q1; lo.z = (u16)q2; lo.w = (u16)q3;
    ((ushort4*)dhi)[i] = hi;
    ((ushort4*)dlo)[i] = lo;
}

__global__ __launch_bounds__(256) void combine_bias(
    const float* __restrict__ bih, const float* __restrict__ bhh, float* __restrict__ out)
{
    const int i = blockIdx.x * 256 + threadIdx.x;
    if (i < G3) out[i] = bih[i] + (i < 2 * HD ? bhh[i] : 0.f);
}

// ---------------------------------------------------------------------------
// Split-bf16 GEMM tile (device fn). BM=128, BN=64, BK=64, K=768 fixed.
// Works inside 256- or 512-thread blocks (compute gated to tid<256).
// ---------------------------------------------------------------------------
#define GP      144
#define SA_HI   0
#define SA_LO   (128 * GP)
#define SW_HI   (2 * 128 * GP)
#define SW_LO   (SW_HI + 64 * GP)
#define STAGE   (SW_LO + 64 * GP)            // 55296
#define GSMEM   (2 * STAGE)                  // 110592

__device__ __forceinline__ void gemm_tile_hl(
    char* smg, unsigned sbase,
    const u16* __restrict__ Ah, const u16* __restrict__ Al,
    const u16* __restrict__ Wh, const u16* __restrict__ Wl,
    const float* __restrict__ bias, float* __restrict__ C,
    int m0, int n0, int N, int ACT)
{
    const int tid  = threadIdx.x;
    const int warp = tid >> 5;
    const int lane = tid & 31;
    const int wm   = warp >> 1;
    const int wn   = warp & 1;
    const int lr   = (tid >> 3) & 31;
    const int lc   = tid & 7;
    const bool act25 = (tid < 256);
    const int K = 768, NS = 12;

    float acc[2][4][4];
#pragma unroll
    for (int mt = 0; mt < 2; mt++)
#pragma unroll
        for (int nt = 0; nt < 4; nt++)
#pragma unroll
            for (int e = 0; e < 4; e++) acc[mt][nt][e] = 0.f;

    const int q  = lane >> 3;
    const int rq = (q & 1) * 8 + (lane & 7);
    const int qk = q >> 1;
    const int l2 = lane & 15;
    const int brow = l2 & 7;
    const int bk16 = ((l2 >> 3) & 1) * 16;

    // slab 0
    if (act25) {
        char* st = smg;
#pragma unroll
        for (int p = 0; p < 4; p++) {
            const int r = lr + p * 32;
            cp16(st + SA_HI + r * GP + lc * 16, Ah + (size_t)(m0 + r) * K + lc * 8);
            cp16(st + SA_LO + r * GP + lc * 16, Al + (size_t)(m0 + r) * K + lc * 8);
        }
#pragma unroll
        for (int p = 0; p < 2; p++) {
            const int r = lr + p * 32;
            cp16(st + SW_HI + r * GP + lc * 16, Wh + (size_t)(n0 + r) * K + lc * 8);
            cp16(st + SW_LO + r * GP + lc * 16, Wl + (size_t)(n0 + r) * K + lc * 8);
        }
        cp_commit();
    }

    for (int s = 0; s < NS; s++) {
        if (s + 1 < NS) {
            if (act25) {
                const int k0 = (s + 1) * 64;
                char* st = smg + ((s + 1) & 1) * STAGE;
#pragma unroll
                for (int p = 0; p < 4; p++) {
                    const int r = lr + p * 32;
                    cp16(st + SA_HI + r * GP + lc * 16, Ah + (size_t)(m0 + r) * K + k0 + lc * 8);
                    cp16(st + SA_LO + r * GP + lc * 16, Al + (size_t)(m0 + r) * K + k0 + lc * 8);
                }
#pragma unroll
                for (int p = 0; p < 2; p++) {
                    const int r = lr + p * 32;
                    cp16(st + SW_HI + r * GP + lc * 16, Wh + (size_t)(n0 + r) * K + k0 + lc * 8);
                    cp16(st + SW_LO + r * GP + lc * 16, Wl + (size_t)(n0 + r) * K + k0 + lc * 8);
                }
                cp_commit();
            }
            cp_wait<1>();
        } else {
            cp_wait<0>();
        }
        __syncthreads();

        if (warp < 8) {
            const unsigned stA_hi = sbase + (s & 1) * STAGE + SA_HI;
            const unsigned stA_lo = sbase + (s & 1) * STAGE + SA_LO;
            const unsigned stW_hi = sbase + (s & 1) * STAGE + SW_HI;
            const unsigned stW_lo = sbase + (s & 1) * STAGE + SW_LO;
#pragma unroll
            for (int kt = 0; kt < 4; kt++) {
                unsigned ah[2][4], al[2][4], bh2[4][2], bl2[4][2];
#pragma unroll
                for (int mt = 0; mt < 2; mt++) {
                    const int row = wm * 32 + mt * 16 + rq;
                    ldmx4(ah[mt], stA_hi + row * GP + kt * 32 + qk * 16);
                    ldmx4(al[mt], stA_lo + row * GP + kt * 32 + qk * 16);
                }
#pragma unroll
                for (int nt = 0; nt < 4; nt++) {
                    const int row = wn * 32 + nt * 8 + brow;
                    ldmx2(bh2[nt], stW_hi + row * GP + kt * 32 + bk16);
                    ldmx2(bl2[nt], stW_lo + row * GP + kt * 32 + bk16);
                }
#pragma unroll
                for (int mt = 0; mt < 2; mt++)
#pragma unroll
                    for (int nt = 0; nt < 4; nt++) {
                        mma16816(acc[mt][nt], ah[mt], bh2[nt]);
                        mma16816(acc[mt][nt], ah[mt], bl2[nt]);
                        mma16816(acc[mt][nt], al[mt], bh2[nt]);
                    }
            }
        }
        __syncthreads();
    }

    if (warp < 8) {
        const float selu_scale = 1.0507009873554804934193349852946f;
        const float selu_alpha = 1.6732632423543772848170429916717f;
        const int r0 = lane >> 2;
        const int c0 = (lane & 3) * 2;
#pragma unroll
        for (int mt = 0; mt < 2; mt++)
#pragma unroll
            for (int nt = 0; nt < 4; nt++) {
                const int col = n0 + wn * 32 + nt * 8 + c0;
                const float b0 = bias[col], b1 = bias[col + 1];
#pragma unroll
                for (int h = 0; h < 2; h++) {
                    const int row = m0 + wm * 32 + mt * 16 + r0 + h * 8;
                    float v0 = acc[mt][nt][h * 2 + 0] + b0;
                    float v1 = acc[mt][nt][h * 2 + 1] + b1;
                    if (ACT == 1) {
                        v0 = selu_scale * (v0 > 0.f ? v0 : selu_alpha * (expf(v0) - 1.f));
                        v1 = selu_scale * (v1 > 0.f ? v1 : selu_alpha * (expf(v1) - 1.f));
                    }
                    *(float2*)(C + (size_t)row * N + col) = make_float2(v0, v1);
                }
            }
    }
}

// Standalone GEMM (xproj0)
__global__ __launch_bounds__(256) void gemm_std(
    const u16* __restrict__ Ah, const u16* __restrict__ Al,
    const u16* __restrict__ Wh, const u16* __restrict__ Wl,
    const float* __restrict__ bias, float* __restrict__ C, int N)
{
    extern __shared__ char smg[];
    unsigned sbase;
    asm("{ .reg .u64 t; cvta.to.shared.u64 t, %1; cvt.u32.u64 %0, t; }"
        : "=r"(sbase) : "l"(smg));
    gemm_tile_hl(smg, sbase, Ah, Al, Wh, Wl, bias, C,
                 blockIdx.y * 128, blockIdx.x * 64, N, 0);
}

// ---------------------------------------------------------------------------
// out_proj (fp32 FFMA2, N=39)
// ---------------------------------------------------------------------------
__global__ __launch_bounds__(256) void gemm_out_tanh(
    const float* __restrict__ A, const float* __restrict__ W,
    const float* __restrict__ bias, float* __restrict__ C,
    int M, int N, int K)
{
    __shared__ float As[8][128];
    __shared__ float Bs[8][128];

    const int tid  = threadIdx.x;
    const int m0   = blockIdx.y * 128;
    const int lrow = tid >> 1;
    const int lk4  = (tid & 1) * 4;
    const int tx = tid & 15;
    const int ty = tid >> 4;

    ull acc2[8][4];
#pragma unroll
    for (int i = 0; i < 8; i++)
#pragma unroll
        for (int j = 0; j < 4; j++) acc2[i][j] = 0ull;

    const float* Arow = A + (size_t)(m0 + lrow) * K + lk4;
    const float* Wrow = W + (size_t)lrow * K + lk4;
    const bool   wok  = lrow < N;

    for (int k0 = 0; k0 < K; k0 += 8) {
        float4 av = *(const float4*)(Arow + k0);
        float4 wv = make_float4(0.f, 0.f, 0.f, 0.f);
        if (wok) wv = *(const float4*)(Wrow + k0);

        __syncthreads();
        As[lk4 + 0][lrow] = av.x; As[lk4 + 1][lrow] = av.y;
        As[lk4 + 2][lrow] = av.z; As[lk4 + 3][lrow] = av.w;
        Bs[lk4 + 0][lrow] = wv.x; Bs[lk4 + 1][lrow] = wv.y;
        Bs[lk4 + 2][lrow] = wv.z; Bs[lk4 + 3][lrow] = wv.w;
        __syncthreads();

#pragma unroll
        for (int kk = 0; kk < 8; kk++) {
            float a[8];
            *(float4*)(a)     = *(const float4*)&As[kk][ty * 4];
            *(float4*)(a + 4) = *(const float4*)&As[kk][64 + ty * 4];
            ulonglong2 b01 = *(const ulonglong2*)&Bs[kk][tx * 4];
            ulonglong2 b23 = *(const ulonglong2*)&Bs[kk][64 + tx * 4];
            ull bb[4] = { b01.x, b01.y, b23.x, b23.y };
            ull aa[8];
#pragma unroll
            for (int i = 0; i < 8; i++) aa[i] = pack2(a[i], a[i]);
#pragma unroll
            for (int i = 0; i < 8; i++)
#pragma unroll
                for (int j = 0; j < 4; j++)
                    fma2(acc2[i][j], aa[i], bb[j]);
        }
    }

#pragma unroll
    for (int i = 0; i < 8; i++) {
        const int m = m0 + ((i < 4) ? (ty * 4 + i) : (64 + ty * 4 + i - 4));
        float* crow = C + (size_t)m * N;
#pragma unroll
        for (int j = 0; j < 4; j++) {
            const int nf = (j < 2) ? (tx * 4 + j * 2) : (64 + tx * 4 + (j - 2) * 2);
            float2 v = unpack2(acc2[i][j]);
            float vals[2] = { v.x, v.y };
#pragma unroll
            for (int s = 0; s < 2; s++) {
                const int n = nf + s;
                if (n < N) crow[n] = tanhf(vals[s] + bias[n]);
            }
        }
    }
}

// ---------------------------------------------------------------------------
// Fused persistent kernel: blocks 0-95 = GRU recurrence (2 batch groups x 48),
// blocks 96-143 = trailing FF-GEMM consumers.
// Recurrence block: 512 threads, 16 units, warp=(k-slice 0..7, n-half 0..1),
// B-frags register-resident, m16 A tile = the group's 16 batches.
// ---------------------------------------------------------------------------
#define HPB      1552
#define OFF_AH   0
#define OFF_AL   24832                       // 16*1552
#define OFF_PRT  49664                       // floats from here: 8*772
#define SCR_HI   0                           // init-only W scratch (24*1552)
#define SCR_LO   37248
#define FUS_SMEM GSMEM                       // 110592 (covers both roles)

__global__ __launch_bounds__(512, 1) void fused_layer(
    const float* __restrict__ xp,            // [B,T,3H] (combined bias folded for r,z)
    const float* __restrict__ w_hh,          // [3H,H] fp32
    const float* __restrict__ b_hh,          // [3H] (n-gate bias used)
    u16* __restrict__ hhi, u16* __restrict__ hlo,
    const u16* __restrict__ cAh, const u16* __restrict__ cAl,
    const u16* __restrict__ cWh, const u16* __restrict__ cWl,
    const float* __restrict__ cbias, float* __restrict__ cC,
    int cN, int cACT, unsigned base_off)
{
    extern __shared__ char smc[];
    unsigned sbase;
    asm("{ .reg .u64 t; cvta.to.shared.u64 t, %1; cvt.u32.u64 %0, t; }"
        : "=r"(sbase) : "l"(smc));
    const int tid = threadIdx.x;

    // ======================= CONSUMER BLOCKS =======================
    if (blockIdx.x >= 96) {
        const int cid = blockIdx.x - 96;
        const unsigned f = ld_acq(&g_flags[0]);
        const unsigned base = (f / 2048u) * 2048u + base_off;
        const int tnt = cN / 64;

        for (int tc = 0; tc < 8; tc++) {
            const unsigned target = base + (unsigned)((tc + 1) * 128);
            if (tid < 96) {
                while ((int)(ld_acq(&g_flags[tid * 32]) - target) < 0) { }
            }
            __syncthreads();
            for (int i = cid; i < 32 * tnt; i += 48) {
                const int b  = i / tnt;
                const int nt = i % tnt;
                gemm_tile_hl(smc, sbase, cAh, cAl, cWh, cWl, cbias, cC,
                             b * TLEN + tc * 128, nt * 64, cN, cACT);
            }
        }
        return;
    }

    // ======================= RECURRENCE BLOCKS =======================
    const int grp  = blockIdx.x / 48;        // batch group (16 batches)
    const int ub   = blockIdx.x % 48;
    const int u0g  = ub * 16;                // unit base
    const int bG0  = grp * 16;               // batch base
    const int warp = tid >> 5;
    const int lane = tid & 31;
    const int ks   = warp >> 1;              // k-slice 0..7 (96 wide)
    const int nh   = warp & 1;               // n-half 0..1 (24 rows)
    const unsigned flag_base = g_flags[blockIdx.x * 32];

    // ---- W init: 2 passes through scratch; frags -> registers ----
    unsigned bh[3][6][2], bl[3][6][2];
    for (int p = 0; p < 2; p++) {
        for (int i = tid; i < 24 * 96; i += 512) {
            const int r  = i / 96;            // scratch row 0..23
            const int kc = (i % 96) * 8;
            const int rg = p * 24 + r;        // gh row 0..47 (gate*16+unit)
            const int gate = rg >> 4, ul = rg & 15;
            const float* ws = w_hh + (size_t)(gate * HD + u0g + ul) * HD + kc;
            float4 a = *(const float4*)(ws);
            float4 b = *(const float4*)(ws + 4);
            unsigned h0 = bfpk(a.y, a.x), h1 = bfpk(a.w, a.z);
            unsigned h2 = bfpk(b.y, b.x), h3 = bfpk(b.w, b.z);
            unsigned l0 = bfpk(a.y - bfhi(h0), a.x - bflo(h0));
            unsigned l1 = bfpk(a.w - bfhi(h1), a.z - bflo(h1));
            unsigned l2_ = bfpk(b.y - bfhi(h2), b.x - bflo(h2));
            unsigned l3 = bfpk(b.w - bfhi(h3), b.z - bflo(h3));
            *(uint4*)(smc + SCR_HI + r * HPB + kc * 2) = make_uint4(h0, h1, h2, h3);
            *(uint4*)(smc + SCR_LO + r * HPB + kc * 2) = make_uint4(l0, l1, l2_, l3);
        }
        __syncthreads();
        if (nh == p) {
            const int l2 = lane & 15;
#pragma unroll
            for (int nt = 0; nt < 3; nt++)
#pragma unroll
                for (int kt = 0; kt < 6; kt++) {
                    const int row = nt * 8 + (l2 & 7);
                    const int kel = ks * 96 + kt * 16 + ((l2 >> 3) & 1) * 8;
                    ldmx2(bh[nt][kt], sbase + SCR_HI + row * HPB + kel * 2);
                    ldmx2(bl[nt][kt], sbase + SCR_LO + row * HPB + kel * 2);
                }
        }
        __syncthreads();
    }

    // ---- gate decode (tid < 256) ----
    const int bg = tid >> 4;                 // local batch 0..15
    const int ug = tid & 15;                 // local unit 0..15
    float bias_n = 0.f, hprev = 0.f;
    if (tid < 256) bias_n = b_hh[2 * HD + u0g + ug];

    // ---- t = 0: gh = 0 (biases folded into xp for r,z) ----
    if (tid < 256) {
        const size_t xb = ((size_t)(bG0 + bg) * TLEN + 0) * G3 + (u0g + ug);
        const float gi_r = xp[xb];
        const float gi_z = xp[xb + HD];
        const float gi_n = xp[xb + 2 * HD];
        const float r = 1.f / (1.f + expf(-gi_r));
        const float z = 1.f / (1.f + expf(-gi_z));
        const float n = tanhf(gi_n + r * bias_n);
        hprev = (1.f - z) * n;
        const size_t hidx = ((size_t)(bG0 + bg) * TLEN + 0) * HD + (u0g + ug);
        unsigned ph = bfpk(hprev, hprev);
        float res = hprev - bflo(ph);
        unsigned pl = bfpk(res, res);
        hhi[hidx] = (u16)ph;
        hlo[hidx] = (u16)pl;
    }
    __syncthreads();
    if (tid == 0) st_rel(&g_flags[blockIdx.x * 32], flag_base + 1u);

    float* prt = (float*)(smc + OFF_PRT);

    for (int t = 1; t < TLEN; t++) {
        // --- poll: 6 source blocks for this warp's k-slice ---
        const unsigned need = flag_base + (unsigned)t;
        if (lane < 6) {
            const unsigned* fp = &g_flags[(grp * 48 + ks * 6 + lane) * 32];
            while ((int)(ld_acq(fp) - need) < 0) { }
        }
        __syncwarp();

        // --- stage: warp (ks,nh) -> rows nh*8..+8, k in [96ks, 96ks+96) ---
        {
            const int row = nh * 8 + (lane >> 2);
            const int seg = lane & 3;
            const size_t sb = ((size_t)(bG0 + row) * TLEN + (t - 1)) * HD
                            + ks * 96 + seg * 24;
            const u16* sh = hhi + sb;
            const u16* sl = hlo + sb;
            char* dh = smc + OFF_AH + row * HPB + (ks * 96 + seg * 24) * 2;
            char* dl = smc + OFF_AL + row * HPB + (ks * 96 + seg * 24) * 2;
#pragma unroll
            for (int j = 0; j < 3; j++) {
                uint4 vh = __ldcg((const uint4*)(sh + j * 8));
                uint4 vl = __ldcg((const uint4*)(sl + j * 8));
                *(uint4*)(dh + j * 16) = vh;
                *(uint4*)(dl + j * 16) = vl;
            }
        }

        // gi prefetch (hidden under mma)
        float gi_r = 0.f, gi_z = 0.f, gi_n = 0.f;
        if (tid < 256) {
            const size_t xb = ((size_t)(bG0 + bg) * TLEN + t) * G3 + (u0g + ug);
            gi_r = xp[xb];
            gi_z = xp[xb + HD];
            gi_n = xp[xb + 2 * HD];
        }
        __syncthreads();

        // --- mma: m16 x (3 n-tiles) x 6 k-tiles, 3 split passes ---
        float acc[3][4];
#pragma unroll
        for (int nt = 0; nt < 3; nt++)
#pragma unroll
            for (int e = 0; e < 4; e++) acc[nt][e] = 0.f;

        const int q = lane >> 3;
        const int rq = (q & 1) * 8 + (lane & 7);
#pragma unroll
        for (int kt = 0; kt < 6; kt++) {
            const int kel = ks * 96 + kt * 16 + (q >> 1) * 8;
            unsigned ah[4], al[4];
            ldmx4(ah, sbase + OFF_AH + rq * HPB + kel * 2);
            ldmx4(al, sbase + OFF_AL + rq * HPB + kel * 2);
#pragma unroll
            for (int nt = 0; nt < 3; nt++) {
                mma16816(acc[nt], ah, bh[nt][kt]);
                mma16816(acc[nt], ah, bl[nt][kt]);
                mma16816(acc[nt], al, bh[nt][kt]);
            }
        }

        // --- dump partials: prt[ks*772 + batch*48 + rowg] ---
        {
            const int r0 = lane >> 2;
            const int c0 = (lane & 3) * 2;
            float* wp = prt + ks * 772;
#pragma unroll
            for (int nt = 0; nt < 3; nt++) {
                const int rowg = nh * 24 + nt * 8 + c0;
                *(float2*)(wp + r0 * 48 + rowg)       = make_float2(acc[nt][0], acc[nt][1]);
                *(float2*)(wp + (r0 + 8) * 48 + rowg) = make_float2(acc[nt][2], acc[nt][3]);
            }
        }
        __syncthreads();

        // --- gates (tid < 256) ---
        if (tid < 256) {
            float gh[3];
#pragma unroll
            for (int g = 0; g < 3; g++) {
                const int o = bg * 48 + g * 16 + ug;
                float s = 0.f;
#pragma unroll
                for (int k = 0; k < 8; k++) s += prt[k * 772 + o];
                gh[g] = s;
            }
            const float r = 1.f / (1.f + expf(-(gi_r + gh[0])));
            const float z = 1.f / (1.f + expf(-(gi_z + gh[1])));
            const float n = tanhf(gi_n + r * (gh[2] + bias_n));
            const float hnew = (1.f - z) * n + z * hprev;
            hprev = hnew;
            const size_t hidx = ((size_t)(bG0 + bg) * TLEN + t) * HD + (u0g + ug);
            unsigned ph = bfpk(hnew, hnew);
            float res = hnew - bflo(ph);
            unsigned pl = bfpk(res, res);
            hhi[hidx] = (u16)ph;
            hlo[hidx] = (u16)pl;
        }
        __syncthreads();

        if (tid == 0) st_rel(&g_flags[blockIdx.x * 32], flag_base + (unsigned)(t + 1));
    }
}

// ---------------------------------------------------------------------------
// Launch
// ---------------------------------------------------------------------------
extern "C" void kernel_launch(void* const* d_in, const int* in_sizes, int n_in,
                              void* d_out, int out_size)
{
    const float* features = (const float*)d_in[0];
    const float* w_ih0 = (const float*)d_in[2];
    const float* w_hh0 = (const float*)d_in[3];
    const float* b_ih0 = (const float*)d_in[4];
    const float* b_hh0 = (const float*)d_in[5];
    const float* w_ih1 = (const float*)d_in[6];
    const float* w_hh1 = (const float*)d_in[7];
    const float* b_ih1 = (const float*)d_in[8];
    const float* b_hh1 = (const float*)d_in[9];
    const float* fc_w  = (const float*)d_in[10];
    const float* fc_b  = (const float*)d_in[11];
    const float* out_w = (const float*)d_in[12];
    const float* out_b = (const float*)d_in[13];

    float *xproj, *xproj2, *fcb, *cb0, *cb1;
    u16 *fh, *fl, *hhi, *hlo, *w0h, *w0l, *w1h, *w1l, *fwh, *fwl;
    cudaGetSymbolAddress((void**)&xproj,  g_xproj);
    cudaGetSymbolAddress((void**)&xproj2, g_xproj2);
    cudaGetSymbolAddress((void**)&fcb,    g_fc);
    cudaGetSymbolAddress((void**)&cb0, g_cb0);
    cudaGetSymbolAddress((void**)&cb1, g_cb1);
    cudaGetSymbolAddress((void**)&fh,  g_fh);
    cudaGetSymbolAddress((void**)&fl,  g_fl);
    cudaGetSymbolAddress((void**)&hhi, g_hhi);
    cudaGetSymbolAddress((void**)&hlo, g_hlo);
    cudaGetSymbolAddress((void**)&w0h, g_w0h);
    cudaGetSymbolAddress((void**)&w0l, g_w0l);
    cudaGetSymbolAddress((void**)&w1h, g_w1h);
    cudaGetSymbolAddress((void**)&w1l, g_w1l);
    cudaGetSymbolAddress((void**)&fwh, g_fwh);
    cudaGetSymbolAddress((void**)&fwl, g_fwl);

    static bool attr_set = false;
    if (!attr_set) {
        cudaFuncSetAttribute(fused_layer,
                             cudaFuncAttributeMaxDynamicSharedMemorySize, (int)FUS_SMEM);
        cudaFuncSetAttribute(gemm_std,
                             cudaFuncAttributeMaxDynamicSharedMemorySize, (int)GSMEM);
        attr_set = true;
    }

    const int M = BSZ * TLEN;

    // Prep: planes + combined biases
    {
        int n4 = (BSZ * TLEN * DIN) / 4;
        pack_hl<<<(n4 + 255) / 256, 256>>>(features, fh, fl, n4);
        n4 = (G3 * DIN) / 4;
        pack_hl<<<(n4 + 255) / 256, 256>>>(w_ih0, w0h, w0l, n4);
        n4 = (G3 * HD) / 4;
        pack_hl<<<(n4 + 255) / 256, 256>>>(w_ih1, w1h, w1l, n4);
        n4 = (FCN * HD) / 4;
        pack_hl<<<(n4 + 255) / 256, 256>>>(fc_w, fwh, fwl, n4);
        combine_bias<<<(G3 + 255) / 256, 256>>>(b_ih0, b_hh0, cb0);
        combine_bias<<<(G3 + 255) / 256, 256>>>(b_ih1, b_hh1, cb1);
    }

    // xproj0 (sequential; first recurrence input)
    gemm_std<<<dim3(G3 / 64, M / 128), 256, GSMEM>>>(
        fh, fl, w0h, w0l, cb0, xproj, G3);

    // Layer 0 recurrence + xproj1 consumers (trailing)
    fused_layer<<<144, 512, FUS_SMEM>>>(
        xproj, w_hh0, b_hh0, hhi, hlo,
        hhi, hlo, w1h, w1l, cb1, xproj2, G3, 0, 0u);

    // Layer 1 recurrence + fc consumers (trailing)
    fused_layer<<<144, 512, FUS_SMEM>>>(
        xproj2, w_hh1, b_hh1, hhi, hlo,
        hhi, hlo, fwh, fwl, fc_b, fcb, FCN, 1, 1024u);

    // out_proj + tanh
    gemm_out_tanh<<<dim3(1, M / 128), 256>>>(fcb, out_w, out_b, (float*)d_out,
                                             M, NOUTC, FCN);
}